// round 2
// baseline (speedup 1.0000x reference)
#include <cuda_runtime.h>
#include <math.h>

#define NB 8
#define NH 16
#define ND 64
#define NS 1024
#define NE 1024

// ---------------- scratch (static device allocations are the sanctioned path) ----
__device__ float g_xh[NH*NB*NS*ND];  // (h,b,s,d) pos-encoded input (residual)
__device__ float g_q [NH*NB*NS*ND];  // (h,b,s,d)
__device__ float g_k [NH*NB*NS*ND];
__device__ float g_v [NH*NB*NS*ND];
__device__ float g_y [NB*NE*NS];     // (b,e,s) pre-layernorm

// ---------------- kernel 1: xh = x + posenc ; q/k/v = tanh(tanh(xh W1+b1) W2+b2) ---
// grid (S/128, B, H), 256 threads. Dynamic smem: sXH[128][65], sZ[128][65], sW[64][68], sB[64]
#define SMEM1_FLOATS (128*65 + 128*65 + 64*68 + 64)

template<bool TOSMEM>
__device__ __forceinline__ void mlp_layer(const float* __restrict__ src,
                                          const float* __restrict__ sW,
                                          const float* __restrict__ sB,
                                          float* __restrict__ dstS,
                                          float* __restrict__ dstG,
                                          int r0, int e0)
{
    float acc[4][8];
    #pragma unroll
    for (int i = 0; i < 4; ++i)
        #pragma unroll
        for (int j = 0; j < 8; ++j) acc[i][j] = 0.f;

    #pragma unroll 8
    for (int d = 0; d < 64; ++d) {
        float a[4];
        #pragma unroll
        for (int i = 0; i < 4; ++i) a[i] = src[(r0+i)*65 + d];
        const float4 w0 = *(const float4*)&sW[d*68 + e0];
        const float4 w1 = *(const float4*)&sW[d*68 + e0 + 4];
        const float wf[8] = {w0.x,w0.y,w0.z,w0.w,w1.x,w1.y,w1.z,w1.w};
        #pragma unroll
        for (int i = 0; i < 4; ++i)
            #pragma unroll
            for (int j = 0; j < 8; ++j) acc[i][j] += a[i]*wf[j];
    }
    if (TOSMEM) {
        #pragma unroll
        for (int i = 0; i < 4; ++i)
            #pragma unroll
            for (int j = 0; j < 8; ++j)
                dstS[(r0+i)*65 + e0 + j] = tanhf(acc[i][j] + sB[e0+j]);
    } else {
        #pragma unroll
        for (int i = 0; i < 4; ++i) {
            float4 o0, o1;
            o0.x = tanhf(acc[i][0] + sB[e0+0]); o0.y = tanhf(acc[i][1] + sB[e0+1]);
            o0.z = tanhf(acc[i][2] + sB[e0+2]); o0.w = tanhf(acc[i][3] + sB[e0+3]);
            o1.x = tanhf(acc[i][4] + sB[e0+4]); o1.y = tanhf(acc[i][5] + sB[e0+5]);
            o1.z = tanhf(acc[i][6] + sB[e0+6]); o1.w = tanhf(acc[i][7] + sB[e0+7]);
            *(float4*)(dstG + (r0+i)*64 + e0)     = o0;
            *(float4*)(dstG + (r0+i)*64 + e0 + 4) = o1;
        }
    }
}

__global__ __launch_bounds__(256) void k_qkv(
    const float* __restrict__ x,
    const float* __restrict__ Wq1, const float* __restrict__ bq1,
    const float* __restrict__ Wq2, const float* __restrict__ bq2,
    const float* __restrict__ Wk1, const float* __restrict__ bk1,
    const float* __restrict__ Wk2, const float* __restrict__ bk2,
    const float* __restrict__ Wv1, const float* __restrict__ bv1,
    const float* __restrict__ Wv2, const float* __restrict__ bv2)
{
    extern __shared__ float sm[];
    float* sXH = sm;                 // [128][65]
    float* sZ  = sXH + 128*65;       // [128][65]
    float* sW  = sZ  + 128*65;       // [64][68]
    float* sB  = sW  + 64*68;        // [64]

    const int tid = threadIdx.x;
    const int h = blockIdx.z, b = blockIdx.y;
    const int s0 = blockIdx.x * 128;

    // xh = x(b, h*64+d, s) + pe(h,s,d); pe flat-reshape: l = h*64 + s/16, e = (s%16)*64 + d
    for (int idx = tid; idx < 128*64; idx += 256) {
        const int d = idx >> 7, si = idx & 127;
        const int s = s0 + si;
        const float xv = x[(b*NE + (h*64 + d))*NS + s];
        const int l = h*64 + (s >> 4);
        const int e = ((s & 15) << 6) | d;
        const float freq = expf((float)(e >> 1) * (-2.0f*9.210340371976184f/1024.0f));
        const float ang = (float)l * freq;
        const float pe = (e & 1) ? cosf(ang) : sinf(ang);
        sXH[si*65 + d] = xv + pe;
    }
    __syncthreads();
    {   // persist xh for the residual (d-contiguous)
        float* dst = g_xh + ((h*NB + b)*NS + s0)*ND;
        for (int idx = tid; idx < 128*16; idx += 256) {
            const int si = idx >> 4, d4 = (idx & 15) * 4;
            float4 vv;
            vv.x = sXH[si*65 + d4 + 0]; vv.y = sXH[si*65 + d4 + 1];
            vv.z = sXH[si*65 + d4 + 2]; vv.w = sXH[si*65 + d4 + 3];
            *(float4*)(dst + si*64 + d4) = vv;
        }
    }

    const float* Wa[3] = {Wq1, Wk1, Wv1};
    const float* Ba[3] = {bq1, bk1, bv1};
    const float* Wb[3] = {Wq2, Wk2, Wv2};
    const float* Bb[3] = {bq2, bk2, bv2};
    float* outs[3] = {g_q, g_k, g_v};

    const int r0 = (tid >> 3) * 4;   // 32 row-groups * 4 rows
    const int e0 = (tid & 7) * 8;    // 8 col-groups * 8 cols

    for (int p = 0; p < 3; ++p) {
        __syncthreads();  // prior users of sW/sZ done
        for (int idx = tid; idx < 64*64; idx += 256) {
            const int d = idx >> 6, e = idx & 63;
            sW[d*68 + e] = Wa[p][(h*64 + d)*64 + e];
        }
        if (tid < 64) sB[tid] = Ba[p][h*64 + tid];
        __syncthreads();
        mlp_layer<true>(sXH, sW, sB, sZ, nullptr, r0, e0);
        __syncthreads();
        for (int idx = tid; idx < 64*64; idx += 256) {
            const int d = idx >> 6, e = idx & 63;
            sW[d*68 + e] = Wb[p][(h*64 + d)*64 + e];
        }
        if (tid < 64) sB[tid] = Bb[p][h*64 + tid];
        __syncthreads();
        float* og = outs[p] + ((h*NB + b)*NS + s0)*ND;
        mlp_layer<false>(sZ, sW, sB, nullptr, og, r0, e0);
    }
}

// ---------------- kernel 2: flash attention (fp32) + residual, writes g_y (b,e,s) ---
// grid (S/128, B, H), 256 threads; smem qT[64][132], kT[64][68], vS[64][68], pS[128][68]
#define SMEM2_FLOATS (64*132 + 64*68 + 64*68 + 128*68)

__global__ __launch_bounds__(256, 2) void k_attn()
{
    extern __shared__ float sm[];
    float* qT = sm;                  // [d][r] transposed, scale folded
    float* kT = qT + 64*132;         // [d][j] transposed
    float* vS = kT + 64*68;          // [j][d]
    float* pS = vS + 64*68;          // [r][j]

    const int tid = threadIdx.x;
    const int h = blockIdx.z, b = blockIdx.y;
    const int s0 = blockIdx.x * 128;
    const int hb = h*NB + b;
    const float* qg = g_q + (hb*NS + s0)*ND;
    const float* kg = g_k + hb*NS*ND;
    const float* vg = g_v + hb*NS*ND;

    for (int idx = tid; idx < 128*64; idx += 256) {
        const int si = idx >> 6, d = idx & 63;
        qT[d*132 + si] = qg[idx] * 0.03125f;   // 1/sqrt(E) folded into q
    }

    const int ty = tid >> 4, tx = tid & 15;
    const int r0 = ty * 8, c0 = tx * 4;

    float m[8], l[8], o[8][4];
    #pragma unroll
    for (int i = 0; i < 8; ++i) {
        m[i] = -INFINITY; l[i] = 0.f;
        o[i][0]=o[i][1]=o[i][2]=o[i][3]=0.f;
    }

    #pragma unroll 1
    for (int kt = 0; kt < 16; ++kt) {
        __syncthreads();
        const float* kgt = kg + kt*64*64;
        const float* vgt = vg + kt*64*64;
        for (int idx = tid; idx < 64*64; idx += 256) {
            const int j = idx >> 6, d = idx & 63;
            kT[d*68 + j] = kgt[idx];
            vS[j*68 + d] = vgt[idx];
        }
        __syncthreads();

        float sc[8][4];
        #pragma unroll
        for (int i = 0; i < 8; ++i) { sc[i][0]=sc[i][1]=sc[i][2]=sc[i][3]=0.f; }

        #pragma unroll 8
        for (int d = 0; d < 64; ++d) {
            const float4 qa = *(const float4*)&qT[d*132 + r0];
            const float4 qb = *(const float4*)&qT[d*132 + r0 + 4];
            const float4 kk = *(const float4*)&kT[d*68 + c0];
            const float qf[8] = {qa.x,qa.y,qa.z,qa.w,qb.x,qb.y,qb.z,qb.w};
            const float kf[4] = {kk.x,kk.y,kk.z,kk.w};
            #pragma unroll
            for (int i = 0; i < 8; ++i)
                #pragma unroll
                for (int jj = 0; jj < 4; ++jj) sc[i][jj] += qf[i]*kf[jj];
        }

        // online softmax; 16 lanes (same ty) share a row group
        #pragma unroll
        for (int i = 0; i < 8; ++i) {
            float mt = fmaxf(fmaxf(sc[i][0], sc[i][1]), fmaxf(sc[i][2], sc[i][3]));
            #pragma unroll
            for (int off = 8; off; off >>= 1)
                mt = fmaxf(mt, __shfl_xor_sync(0xffffffffu, mt, off));
            const float mn = fmaxf(m[i], mt);
            const float corr = __expf(m[i] - mn);
            float p0 = __expf(sc[i][0] - mn), p1 = __expf(sc[i][1] - mn);
            float p2 = __expf(sc[i][2] - mn), p3 = __expf(sc[i][3] - mn);
            *(float4*)&pS[(r0+i)*68 + c0] = make_float4(p0, p1, p2, p3);
            float ssum = (p0 + p1) + (p2 + p3);
            #pragma unroll
            for (int off = 8; off; off >>= 1)
                ssum += __shfl_xor_sync(0xffffffffu, ssum, off);
            l[i] = l[i]*corr + ssum;
            m[i] = mn;
            o[i][0]*=corr; o[i][1]*=corr; o[i][2]*=corr; o[i][3]*=corr;
        }
        __syncthreads();

        #pragma unroll 8
        for (int j = 0; j < 64; ++j) {
            const float4 vv = *(const float4*)&vS[j*68 + c0];
            #pragma unroll
            for (int i = 0; i < 8; ++i) {
                const float pp = pS[(r0+i)*68 + j];
                o[i][0] += pp*vv.x; o[i][1] += pp*vv.y;
                o[i][2] += pp*vv.z; o[i][3] += pp*vv.w;
            }
        }
    }

    __syncthreads();
    {   // finalize: o/l + residual, stage in pS, then transposed coalesced store
        const float* xg = g_xh + (hb*NS + s0)*ND;
        #pragma unroll
        for (int i = 0; i < 8; ++i) {
            const float inv = 1.0f / l[i];
            const float4 xr = *(const float4*)&xg[(r0+i)*64 + c0];
            float4 ov;
            ov.x = o[i][0]*inv + xr.x; ov.y = o[i][1]*inv + xr.y;
            ov.z = o[i][2]*inv + xr.z; ov.w = o[i][3]*inv + xr.w;
            *(float4*)&pS[(r0+i)*68 + c0] = ov;
        }
    }
    __syncthreads();
    {
        float* yg = g_y + (size_t)b*NE*NS + (size_t)(h*64)*NS + s0;
        for (int idx = tid; idx < 64*128; idx += 256) {
            const int d = idx >> 7, si = idx & 127;
            yg[d*NS + si] = pS[si*68 + d];
        }
    }
}

// ---------------- kernel 3: layernorm over E per (b,s), output (B,E,S) --------------
__global__ __launch_bounds__(256) void k_ln(const float* __restrict__ gamma,
                                            const float* __restrict__ beta,
                                            float* __restrict__ out)
{
    __shared__ float rsum[8][33];
    __shared__ float rsq [8][33];
    __shared__ float smu[32], srs[32];
    const int tid = threadIdx.x;
    const int sl = tid & 31, eg = tid >> 5;
    const int b = blockIdx.y;
    const int s = blockIdx.x*32 + sl;
    const float* yb = g_y + (size_t)b*NE*NS + s;

    float sum = 0.f, sq = 0.f;
    #pragma unroll 4
    for (int e = eg; e < NE; e += 8) {
        const float v = yb[(size_t)e*NS];
        sum += v; sq += v*v;
    }
    rsum[eg][sl] = sum; rsq[eg][sl] = sq;
    __syncthreads();
    if (eg == 0) {
        float ts = 0.f, tq = 0.f;
        #pragma unroll
        for (int g = 0; g < 8; ++g) { ts += rsum[g][sl]; tq += rsq[g][sl]; }
        const float mu = ts * (1.0f/1024.0f);
        const float var = tq * (1.0f/1024.0f) - mu*mu;
        smu[sl] = mu; srs[sl] = rsqrtf(var + 1e-5f);
    }
    __syncthreads();
    const float mu = smu[sl], rs = srs[sl];
    float* ob = out + (size_t)b*NE*NS + s;
    #pragma unroll 4
    for (int e = eg; e < NE; e += 8) {
        const float v = yb[(size_t)e*NS];
        ob[(size_t)e*NS] = (v - mu)*rs*__ldg(&gamma[e]) + __ldg(&beta[e]);
    }
}

// ---------------- launcher ----------------------------------------------------------
extern "C" void kernel_launch(void* const* d_in, const int* in_sizes, int n_in,
                              void* d_out, int out_size)
{
    (void)in_sizes; (void)n_in; (void)out_size;
    const float* x   = (const float*)d_in[0];
    const float* Wq1 = (const float*)d_in[1];  const float* bq1 = (const float*)d_in[2];
    const float* Wq2 = (const float*)d_in[3];  const float* bq2 = (const float*)d_in[4];
    const float* Wk1 = (const float*)d_in[5];  const float* bk1 = (const float*)d_in[6];
    const float* Wk2 = (const float*)d_in[7];  const float* bk2 = (const float*)d_in[8];
    const float* Wv1 = (const float*)d_in[9];  const float* bv1 = (const float*)d_in[10];
    const float* Wv2 = (const float*)d_in[11]; const float* bv2 = (const float*)d_in[12];
    const float* gamma = (const float*)d_in[13];
    const float* beta  = (const float*)d_in[14];
    float* out = (float*)d_out;

    const int smem1 = SMEM1_FLOATS * (int)sizeof(float);
    const int smem2 = SMEM2_FLOATS * (int)sizeof(float);
    cudaFuncSetAttribute(k_qkv,  cudaFuncAttributeMaxDynamicSharedMemorySize, smem1);
    cudaFuncSetAttribute(k_attn, cudaFuncAttributeMaxDynamicSharedMemorySize, smem2);

    dim3 g1(NS/128, NB, NH);
    k_qkv<<<g1, 256, smem1>>>(x, Wq1, bq1, Wq2, bq2, Wk1, bk1, Wk2, bk2, Wv1, bv1, Wv2, bv2);

    dim3 g2(NS/128, NB, NH);
    k_attn<<<g2, 256, smem2>>>();

    dim3 g3(NS/32, NB);
    k_ln<<<g3, 256>>>(gamma, beta, out);
}

// round 3
// speedup vs baseline: 1.7110x; 1.7110x over previous
#include <cuda_runtime.h>
#include <math.h>
#include <stdint.h>

#define NB 8
#define NH 16
#define ND 64
#define NS 1024
#define NE 1024

#define PADA 68   // pad for A-operand / K-as-B arrays (bank-bijective)
#define PADV 76   // pad for V-as-B array (bank-bijective)

// ---------------- scratch ----------------
__device__ float g_xh[NH*NB*NS*ND];  // (h,b,s,d) pos-encoded input (residual)
__device__ float g_q [NH*NB*NS*ND];
__device__ float g_k [NH*NB*NS*ND];
__device__ float g_v [NH*NB*NS*ND];
__device__ float g_y [NB*NE*NS];     // (b,e,s) pre-layernorm

// ---------------- tf32 helpers ----------------
__device__ __forceinline__ float f2tf(float x) {
    uint32_t r;
    asm("cvt.rna.tf32.f32 %0, %1;" : "=r"(r) : "f"(x));
    return __uint_as_float(r);
}

__device__ __forceinline__ void mma8(float* c, const float* a, const float* b) {
    asm volatile(
        "mma.sync.aligned.m16n8k8.row.col.f32.tf32.tf32.f32 "
        "{%0,%1,%2,%3}, {%4,%5,%6,%7}, {%8,%9}, {%0,%1,%2,%3};\n"
        : "+f"(c[0]), "+f"(c[1]), "+f"(c[2]), "+f"(c[3])
        : "r"(__float_as_uint(a[0])), "r"(__float_as_uint(a[1])),
          "r"(__float_as_uint(a[2])), "r"(__float_as_uint(a[3])),
          "r"(__float_as_uint(b[0])), "r"(__float_as_uint(b[1])));
}

// ---------------- kernel 1: posenc + QKV MLPs (tf32 MMA) ----------------
// grid (S/128, B, H), 256 threads. smem: sXH[128][68], sZ[128][68], sWT[64][68]
#define SMEM1_FLOATS (128*PADA + 128*PADA + 64*PADA)

template<bool TOSMEM>
__device__ __forceinline__ void qkv_layer(const float* __restrict__ sA,
                                          const float* __restrict__ sWT,
                                          const float* __restrict__ biasg,
                                          float* __restrict__ sOut,
                                          float* __restrict__ gOut,
                                          int rA, int gid, int t4)
{
    float cc[8][4];
    #pragma unroll
    for (int nt = 0; nt < 8; ++nt) { cc[nt][0]=cc[nt][1]=cc[nt][2]=cc[nt][3]=0.f; }

    #pragma unroll
    for (int ks = 0; ks < 8; ++ks) {
        const int ac = ks*8 + t4;
        float a[4];
        a[0] = sA[rA*PADA + ac];
        a[1] = sA[(rA+8)*PADA + ac];
        a[2] = sA[rA*PADA + ac + 4];
        a[3] = sA[(rA+8)*PADA + ac + 4];
        #pragma unroll
        for (int nt = 0; nt < 8; ++nt) {
            float bb[2];
            bb[0] = sWT[(nt*8+gid)*PADA + ac];      // W^T[e][d], B[d][e]
            bb[1] = sWT[(nt*8+gid)*PADA + ac + 4];
            mma8(cc[nt], a, bb);
        }
    }

    float2 bv[8];
    #pragma unroll
    for (int nt = 0; nt < 8; ++nt)
        bv[nt] = *(const float2*)&biasg[nt*8 + t4*2];

    #pragma unroll
    for (int nt = 0; nt < 8; ++nt) {
        const int col = nt*8 + t4*2;
        #pragma unroll
        for (int r = 0; r < 2; ++r) {
            const int row = rA + 8*r;
            const float z0 = tanhf(cc[nt][2*r]   + bv[nt].x);
            const float z1 = tanhf(cc[nt][2*r+1] + bv[nt].y);
            if (TOSMEM)
                *(float2*)&sOut[row*PADA + col] = make_float2(f2tf(z0), f2tf(z1));
            else
                *(float2*)&gOut[row*64 + col] = make_float2(z0, z1);
        }
    }
}

__global__ __launch_bounds__(256, 2) void k_qkv(
    const float* __restrict__ x,
    const float* __restrict__ Wq1, const float* __restrict__ bq1,
    const float* __restrict__ Wq2, const float* __restrict__ bq2,
    const float* __restrict__ Wk1, const float* __restrict__ bk1,
    const float* __restrict__ Wk2, const float* __restrict__ bk2,
    const float* __restrict__ Wv1, const float* __restrict__ bv1,
    const float* __restrict__ Wv2, const float* __restrict__ bv2)
{
    extern __shared__ float sm[];
    float* sXH = sm;                  // [128][PADA]
    float* sZ  = sXH + 128*PADA;      // [128][PADA]
    float* sWT = sZ  + 128*PADA;      // [64][PADA]  (W transposed: [e][d])

    const int tid = threadIdx.x;
    const int h = blockIdx.z, b = blockIdx.y;
    const int s0 = blockIdx.x * 128;

    // xh = x + posenc (exact fp32)
    for (int idx = tid; idx < 128*64; idx += 256) {
        const int d = idx >> 7, si = idx & 127;
        const int s = s0 + si;
        const float xv = x[(b*NE + (h*64 + d))*NS + s];
        const int l = h*64 + (s >> 4);
        const int e = ((s & 15) << 6) | d;
        const float freq = expf((float)(e >> 1) * (-2.0f*9.210340371976184f/1024.0f));
        const float ang = (float)l * freq;
        const float pe = (e & 1) ? cosf(ang) : sinf(ang);
        sXH[si*PADA + d] = xv + pe;
    }
    __syncthreads();
    {   // persist exact xh for the residual
        float* dst = g_xh + ((h*NB + b)*NS + s0)*ND;
        for (int idx = tid; idx < 128*16; idx += 256) {
            const int si = idx >> 4, d4 = (idx & 15) * 4;
            float4 vv = *(float4*)&sXH[si*PADA + d4];
            *(float4*)(dst + si*64 + d4) = vv;
        }
    }
    __syncthreads();
    // round sXH to tf32 in place (flat, padding included -- harmless)
    for (int idx = tid; idx < 128*PADA; idx += 256) sXH[idx] = f2tf(sXH[idx]);

    const float* Wa[3] = {Wq1, Wk1, Wv1};
    const float* Ba[3] = {bq1, bk1, bv1};
    const float* Wb[3] = {Wq2, Wk2, Wv2};
    const float* Bb[3] = {bq2, bk2, bv2};
    float* outs[3] = {g_q, g_k, g_v};

    const int lane = tid & 31, wid = tid >> 5;
    const int gid = lane >> 2, t4 = lane & 3;
    const int rA = wid*16 + gid;

    for (int p = 0; p < 3; ++p) {
        __syncthreads();
        for (int idx = tid; idx < 64*64; idx += 256) {
            const int d = idx >> 6, e = idx & 63;
            sWT[e*PADA + d] = f2tf(Wa[p][h*4096 + idx]);
        }
        __syncthreads();
        qkv_layer<true>(sXH, sWT, Ba[p] + h*64, sZ, nullptr, rA, gid, t4);
        __syncthreads();
        for (int idx = tid; idx < 64*64; idx += 256) {
            const int d = idx >> 6, e = idx & 63;
            sWT[e*PADA + d] = f2tf(Wb[p][h*4096 + idx]);
        }
        __syncthreads();
        float* og = outs[p] + ((h*NB + b)*NS + s0)*ND;
        qkv_layer<false>(sZ, sWT, Bb[p] + h*64, nullptr, og, rA, gid, t4);
    }
}

// ---------------- kernel 2: flash attention (tf32 MMA) + residual ----------------
// grid (S/128, B, H), 256 threads
#define SMEM2_FLOATS (128*PADA + 64*PADA + 64*PADV + 128*PADA)

__global__ __launch_bounds__(256, 2) void k_attn()
{
    extern __shared__ float sm[];
    float* sQ = sm;                   // [128][PADA] row-major [s][d], tf32, scale folded
    float* sK = sQ + 128*PADA;        // [64][PADA]  row-major [j][d], tf32
    float* sV = sK + 64*PADA;         // [64][PADV]  row-major [j][d], tf32
    float* sP = sV + 64*PADV;         // [128][PADA] P staging / output staging

    const int tid = threadIdx.x;
    const int lane = tid & 31, wid = tid >> 5;
    const int gid = lane >> 2, t4 = lane & 3;
    const int rA = wid*16 + gid;

    const int h = blockIdx.z, b = blockIdx.y;
    const int s0 = blockIdx.x * 128;
    const int hb = h*NB + b;
    const float* qg = g_q + (hb*NS + s0)*ND;
    const float* kg = g_k + hb*NS*ND;
    const float* vg = g_v + hb*NS*ND;

    for (int idx = tid; idx < 128*64; idx += 256) {
        const int si = idx >> 6, d = idx & 63;
        sQ[si*PADA + d] = f2tf(qg[idx] * 0.03125f);   // 1/sqrt(E) folded
    }

    float m2[2] = {-INFINITY, -INFINITY};
    float l2[2] = {0.f, 0.f};
    float o[8][4];
    #pragma unroll
    for (int nt = 0; nt < 8; ++nt) { o[nt][0]=o[nt][1]=o[nt][2]=o[nt][3]=0.f; }

    #pragma unroll 1
    for (int kt = 0; kt < 16; ++kt) {
        __syncthreads();
        const float* kgt = kg + kt*4096;
        const float* vgt = vg + kt*4096;
        for (int idx = tid; idx < 64*64; idx += 256) {
            const int j = idx >> 6, d = idx & 63;
            sK[j*PADA + d] = f2tf(kgt[idx]);
            sV[j*PADV + d] = f2tf(vgt[idx]);
        }
        __syncthreads();

        // ---- scores = Q K^T ----
        float sc[8][4];
        #pragma unroll
        for (int nt = 0; nt < 8; ++nt) { sc[nt][0]=sc[nt][1]=sc[nt][2]=sc[nt][3]=0.f; }

        #pragma unroll
        for (int ks = 0; ks < 8; ++ks) {
            const int ac = ks*8 + t4;
            float a[4];
            a[0] = sQ[rA*PADA + ac];
            a[1] = sQ[(rA+8)*PADA + ac];
            a[2] = sQ[rA*PADA + ac + 4];
            a[3] = sQ[(rA+8)*PADA + ac + 4];
            #pragma unroll
            for (int nt = 0; nt < 8; ++nt) {
                float bb[2];
                bb[0] = sK[(nt*8+gid)*PADA + ac];     // B[d][j] = k[j][d]
                bb[1] = sK[(nt*8+gid)*PADA + ac + 4];
                mma8(sc[nt], a, bb);
            }
        }

        // ---- online softmax (quad owns a row: lanes differ only in t4) ----
        #pragma unroll
        for (int r = 0; r < 2; ++r) {
            const int row = rA + 8*r;
            float mt = -INFINITY;
            #pragma unroll
            for (int nt = 0; nt < 8; ++nt)
                mt = fmaxf(mt, fmaxf(sc[nt][2*r], sc[nt][2*r+1]));
            mt = fmaxf(mt, __shfl_xor_sync(0xffffffffu, mt, 1));
            mt = fmaxf(mt, __shfl_xor_sync(0xffffffffu, mt, 2));
            const float mn = fmaxf(m2[r], mt);
            const float corr = __expf(m2[r] - mn);
            float ssum = 0.f;
            #pragma unroll
            for (int nt = 0; nt < 8; ++nt) {
                const float p0 = __expf(sc[nt][2*r]   - mn);
                const float p1 = __expf(sc[nt][2*r+1] - mn);
                ssum += p0 + p1;
                *(float2*)&sP[row*PADA + nt*8 + t4*2] = make_float2(f2tf(p0), f2tf(p1));
            }
            ssum += __shfl_xor_sync(0xffffffffu, ssum, 1);
            ssum += __shfl_xor_sync(0xffffffffu, ssum, 2);
            l2[r] = l2[r]*corr + ssum;
            m2[r] = mn;
            #pragma unroll
            for (int nt = 0; nt < 8; ++nt) { o[nt][2*r] *= corr; o[nt][2*r+1] *= corr; }
        }
        __syncwarp();

        // ---- O += P V ----
        #pragma unroll
        for (int ks = 0; ks < 8; ++ks) {
            const int ac = ks*8 + t4;
            float a[4];
            a[0] = sP[rA*PADA + ac];
            a[1] = sP[(rA+8)*PADA + ac];
            a[2] = sP[rA*PADA + ac + 4];
            a[3] = sP[(rA+8)*PADA + ac + 4];
            #pragma unroll
            for (int dt = 0; dt < 8; ++dt) {
                float bb[2];
                bb[0] = sV[(ks*8+t4)*PADV + dt*8+gid];     // B[j][d] = v[j][d]
                bb[1] = sV[(ks*8+t4+4)*PADV + dt*8+gid];
                mma8(o[dt], a, bb);
            }
        }
    }

    // ---- finalize: o/l + residual, stage, transposed store ----
    __syncthreads();
    {
        const float* xg = g_xh + (hb*NS + s0)*ND;
        #pragma unroll
        for (int r = 0; r < 2; ++r) {
            const float inv = 1.0f / l2[r];
            const int row = rA + 8*r;
            #pragma unroll
            for (int dt = 0; dt < 8; ++dt) {
                const int col = dt*8 + t4*2;
                const float2 xr = *(const float2*)&xg[row*64 + col];
                *(float2*)&sP[row*PADA + col] =
                    make_float2(o[dt][2*r]*inv + xr.x, o[dt][2*r+1]*inv + xr.y);
            }
        }
    }
    __syncthreads();
    {
        float* yg = g_y + (size_t)b*NE*NS + (size_t)(h*64)*NS + s0;
        for (int idx = tid; idx < 64*128; idx += 256) {
            const int d = idx >> 7, si = idx & 127;
            yg[d*NS + si] = sP[si*PADA + d];
        }
    }
}

// ---------------- kernel 3: layernorm ----------------
__global__ __launch_bounds__(256) void k_ln(const float* __restrict__ gamma,
                                            const float* __restrict__ beta,
                                            float* __restrict__ out)
{
    __shared__ float rsum[8][33];
    __shared__ float rsq [8][33];
    __shared__ float smu[32], srs[32];
    const int tid = threadIdx.x;
    const int sl = tid & 31, eg = tid >> 5;
    const int b = blockIdx.y;
    const int s = blockIdx.x*32 + sl;
    const float* yb = g_y + (size_t)b*NE*NS + s;

    float sum = 0.f, sq = 0.f;
    #pragma unroll 4
    for (int e = eg; e < NE; e += 8) {
        const float v = yb[(size_t)e*NS];
        sum += v; sq += v*v;
    }
    rsum[eg][sl] = sum; rsq[eg][sl] = sq;
    __syncthreads();
    if (eg == 0) {
        float ts = 0.f, tq = 0.f;
        #pragma unroll
        for (int g = 0; g < 8; ++g) { ts += rsum[g][sl]; tq += rsq[g][sl]; }
        const float mu = ts * (1.0f/1024.0f);
        const float var = tq * (1.0f/1024.0f) - mu*mu;
        smu[sl] = mu; srs[sl] = rsqrtf(var + 1e-5f);
    }
    __syncthreads();
    const float mu = smu[sl], rs = srs[sl];
    float* ob = out + (size_t)b*NE*NS + s;
    #pragma unroll 4
    for (int e = eg; e < NE; e += 8) {
        const float v = yb[(size_t)e*NS];
        ob[(size_t)e*NS] = (v - mu)*rs*__ldg(&gamma[e]) + __ldg(&beta[e]);
    }
}

// ---------------- launcher ----------------
extern "C" void kernel_launch(void* const* d_in, const int* in_sizes, int n_in,
                              void* d_out, int out_size)
{
    (void)in_sizes; (void)n_in; (void)out_size;
    const float* x   = (const float*)d_in[0];
    const float* Wq1 = (const float*)d_in[1];  const float* bq1 = (const float*)d_in[2];
    const float* Wq2 = (const float*)d_in[3];  const float* bq2 = (const float*)d_in[4];
    const float* Wk1 = (const float*)d_in[5];  const float* bk1 = (const float*)d_in[6];
    const float* Wk2 = (const float*)d_in[7];  const float* bk2 = (const float*)d_in[8];
    const float* Wv1 = (const float*)d_in[9];  const float* bv1 = (const float*)d_in[10];
    const float* Wv2 = (const float*)d_in[11]; const float* bv2 = (const float*)d_in[12];
    const float* gamma = (const float*)d_in[13];
    const float* beta  = (const float*)d_in[14];
    float* out = (float*)d_out;

    const int smem1 = SMEM1_FLOATS * (int)sizeof(float);
    const int smem2 = SMEM2_FLOATS * (int)sizeof(float);
    cudaFuncSetAttribute(k_qkv,  cudaFuncAttributeMaxDynamicSharedMemorySize, smem1);
    cudaFuncSetAttribute(k_attn, cudaFuncAttributeMaxDynamicSharedMemorySize, smem2);

    dim3 g1(NS/128, NB, NH);
    k_qkv<<<g1, 256, smem1>>>(x, Wq1, bq1, Wq2, bq2, Wk1, bk1, Wk2, bk2, Wv1, bv1, Wv2, bv2);

    dim3 g2(NS/128, NB, NH);
    k_attn<<<g2, 256, smem2>>>();

    dim3 g3(NS/32, NB);
    k_ln<<<g3, 256>>>(gamma, beta, out);
}

// round 5
// speedup vs baseline: 1.7801x; 1.0404x over previous
#include <cuda_runtime.h>
#include <math.h>
#include <stdint.h>

#define NB 8
#define NH 16
#define ND 64
#define NS 1024
#define NE 1024

#define PADP 68   // row-major pad: row*68 mod 32 = gid*4 -> conflict-free quad loads

// ---------------- scratch ----------------
__device__ float g_xh[NH*NB*NS*ND];  // (h,b,s,d) pos-encoded input (residual)
__device__ float g_q [NH*NB*NS*ND];
__device__ float g_k [NH*NB*NS*ND];
__device__ float g_v [NH*NB*NS*ND];
__device__ float g_y [NB*NE*NS];     // (b,e,s) pre-layernorm

// ---------------- helpers ----------------
__device__ __forceinline__ float f2tf(float x) {
    uint32_t r;
    asm("cvt.rna.tf32.f32 %0, %1;" : "=r"(r) : "f"(x));
    return __uint_as_float(r);
}

__device__ __forceinline__ float ftanh(float x) {
    const float e = __expf(2.0f * x);
    return 1.0f - __fdividef(2.0f, e + 1.0f);
}

__device__ __forceinline__ void mma8(float* c, const float* a, const float* b) {
    asm volatile(
        "mma.sync.aligned.m16n8k8.row.col.f32.tf32.tf32.f32 "
        "{%0,%1,%2,%3}, {%4,%5,%6,%7}, {%8,%9}, {%0,%1,%2,%3};\n"
        : "+f"(c[0]), "+f"(c[1]), "+f"(c[2]), "+f"(c[3])
        : "r"(__float_as_uint(a[0])), "r"(__float_as_uint(a[1])),
          "r"(__float_as_uint(a[2])), "r"(__float_as_uint(a[3])),
          "r"(__float_as_uint(b[0])), "r"(__float_as_uint(b[1])));
}

// Fragment layouts (lane = gid*4+t4 == laneid):
//  A-frag (128x64): sAf[((w*8+ks)*32 + lane)*4 + (r + 2*hi)]
//      = A[w*16+gid+8*r][ks*8+t4+4*hi]          -> one LDS.128 per (w,ks)
//  B-frag (64 n x 64 k): sBf[((nt*8+ks)*32 + lane)*2 + hi]
//      = Bn[nt*8+gid][ks*8+t4+4*hi]             -> one LDS.64 per (nt,ks)

// ---------------- kernel 1: posenc + QKV MLPs ----------------
// smem: sXHf[8192] A-frag, sZ[128*PADP] row-major, sWf[4096] B-frag
#define SMEM1_FLOATS (8192 + 128*PADP + 4096)

template<bool AFRAG, bool TOSMEM>
__device__ __forceinline__ void qkv_layer(const float* __restrict__ sA,
                                          const float* __restrict__ sWf,
                                          const float* __restrict__ biasg,
                                          float* __restrict__ sOut,
                                          float* __restrict__ gOut,
                                          int wid, int lane, int gid, int t4)
{
    const int rA = wid*16 + gid;
    float cc[8][4];
    #pragma unroll
    for (int nt = 0; nt < 8; ++nt) { cc[nt][0]=cc[nt][1]=cc[nt][2]=cc[nt][3]=0.f; }

    #pragma unroll
    for (int ks = 0; ks < 8; ++ks) {
        float a[4];
        if (AFRAG) {
            const float4 av = *(const float4*)&sA[((wid*8+ks)*32 + lane)*4];
            a[0]=av.x; a[1]=av.y; a[2]=av.z; a[3]=av.w;
        } else {
            const int ac = ks*8 + t4;
            a[0] = sA[rA*PADP + ac];
            a[1] = sA[(rA+8)*PADP + ac];
            a[2] = sA[rA*PADP + ac + 4];
            a[3] = sA[(rA+8)*PADP + ac + 4];
        }
        #pragma unroll
        for (int nt = 0; nt < 8; ++nt) {
            const float2 bb = *(const float2*)&sWf[((nt*8+ks)*32 + lane)*2];
            mma8(cc[nt], a, (const float*)&bb);
        }
    }

    float2 bv[8];
    #pragma unroll
    for (int nt = 0; nt < 8; ++nt)
        bv[nt] = *(const float2*)&biasg[nt*8 + t4*2];

    #pragma unroll
    for (int nt = 0; nt < 8; ++nt) {
        const int col = nt*8 + t4*2;
        #pragma unroll
        for (int r = 0; r < 2; ++r) {
            const int row = rA + 8*r;
            const float z0 = ftanh(cc[nt][2*r]   + bv[nt].x);
            const float z1 = ftanh(cc[nt][2*r+1] + bv[nt].y);
            if (TOSMEM)
                *(float2*)&sOut[row*PADP + col] = make_float2(f2tf(z0), f2tf(z1));
            else
                *(float2*)&gOut[row*64 + col] = make_float2(z0, z1);
        }
    }
}

__global__ __launch_bounds__(256, 2) void k_qkv(
    const float* __restrict__ x,
    const float* __restrict__ Wq1, const float* __restrict__ bq1,
    const float* __restrict__ Wq2, const float* __restrict__ bq2,
    const float* __restrict__ Wk1, const float* __restrict__ bk1,
    const float* __restrict__ Wk2, const float* __restrict__ bk2,
    const float* __restrict__ Wv1, const float* __restrict__ bv1,
    const float* __restrict__ Wv2, const float* __restrict__ bv2)
{
    extern __shared__ float sm[];
    float* sXHf = sm;                 // [8192] A-frag of xh (tf32)
    float* sZ   = sXHf + 8192;        // [128][PADP] row-major
    float* sWf  = sZ + 128*PADP;      // [4096] B-frag of W (tf32)

    const int tid = threadIdx.x;
    const int lane = tid & 31, wid = tid >> 5;
    const int gid = lane >> 2, t4 = lane & 3;
    const int h = blockIdx.z, b = blockIdx.y;
    const int s0 = blockIdx.x * 128;

    // xh = x + posenc (exact fp32) -> sZ row-major
    for (int idx = tid; idx < 128*64; idx += 256) {
        const int d = idx >> 7, si = idx & 127;
        const int s = s0 + si;
        const float xv = x[(b*NE + (h*64 + d))*NS + s];
        const int l = h*64 + (s >> 4);
        const int e = ((s & 15) << 6) | d;
        const float freq = expf((float)(e >> 1) * (-2.0f*9.210340371976184f/1024.0f));
        const float ang = (float)l * freq;
        const float pe = (e & 1) ? cosf(ang) : sinf(ang);
        sZ[si*PADP + d] = xv + pe;
    }
    __syncthreads();
    {   // persist exact xh for residual; permute tf32 copy into A-frag
        float* dst = g_xh + ((h*NB + b)*NS + s0)*ND;
        for (int idx = tid; idx < 128*16; idx += 256) {
            const int si = idx >> 4, d4 = (idx & 15) * 4;
            *(float4*)(dst + si*64 + d4) = *(float4*)&sZ[si*PADP + d4];
        }
        for (int idx = tid; idx < 128*64; idx += 256) {
            const int si = idx >> 6, d = idx & 63;
            const int w = si >> 4, g8 = si & 7, r = (si >> 3) & 1;
            const int ks = d >> 3, tt = d & 3, hi = (d >> 2) & 1;
            sXHf[((w*8+ks)*32 + g8*4 + tt)*4 + r + 2*hi] = f2tf(sZ[si*PADP + d]);
        }
    }

    const float* Wa[3] = {Wq1, Wk1, Wv1};
    const float* Ba[3] = {bq1, bk1, bv1};
    const float* Wb[3] = {Wq2, Wk2, Wv2};
    const float* Bb[3] = {bq2, bk2, bv2};
    float* outs[3] = {g_q, g_k, g_v};

    for (int p = 0; p < 3; ++p) {
        __syncthreads();
        for (int idx = tid; idx < 64*64; idx += 256) {   // W1 -> B-frag
            const int d = idx >> 6, e = idx & 63;
            const int nt = e >> 3, g8 = e & 7;
            const int ks = d >> 3, tt = d & 3, hi = (d >> 2) & 1;
            sWf[((nt*8+ks)*32 + g8*4 + tt)*2 + hi] = f2tf(Wa[p][h*4096 + idx]);
        }
        __syncthreads();
        qkv_layer<true, true>(sXHf, sWf, Ba[p] + h*64, sZ, nullptr, wid, lane, gid, t4);
        __syncthreads();
        for (int idx = tid; idx < 64*64; idx += 256) {   // W2 -> B-frag
            const int d = idx >> 6, e = idx & 63;
            const int nt = e >> 3, g8 = e & 7;
            const int ks = d >> 3, tt = d & 3, hi = (d >> 2) & 1;
            sWf[((nt*8+ks)*32 + g8*4 + tt)*2 + hi] = f2tf(Wb[p][h*4096 + idx]);
        }
        __syncthreads();
        float* og = outs[p] + ((h*NB + b)*NS + s0)*ND;
        qkv_layer<false, false>(sZ, sWf, Bb[p] + h*64, nullptr, og, wid, lane, gid, t4);
    }
}

// ---------------- kernel 2: flash attention (tf32 MMA, frag-staged) ----------------
#define SMEM2_FLOATS (8192 + 4096 + 4096 + 128*PADP)

__global__ __launch_bounds__(256, 2) void k_attn()
{
    extern __shared__ float sm[];
    float* sQf = sm;                  // [8192] A-frag of Q (tf32, scale folded)
    float* sKf = sQf + 8192;          // [4096] B-frag of K
    float* sVf = sKf + 4096;          // [4096] B-frag of V
    float* sP  = sVf + 4096;          // [128][PADP] P / output staging

    const int tid = threadIdx.x;
    const int lane = tid & 31, wid = tid >> 5;
    const int gid = lane >> 2, t4 = lane & 3;
    const int rA = wid*16 + gid;

    const int h = blockIdx.z, b = blockIdx.y;
    const int s0 = blockIdx.x * 128;
    const int hb = h*NB + b;
    const float* qg = g_q + (hb*NS + s0)*ND;
    const float* kg = g_k + hb*NS*ND;
    const float* vg = g_v + hb*NS*ND;

    // Q -> A-frag (one-time)
    for (int idx = tid; idx < 128*64; idx += 256) {
        const int si = idx >> 6, d = idx & 63;
        const int w = si >> 4, g8 = si & 7, r = (si >> 3) & 1;
        const int ks = d >> 3, tt = d & 3, hi = (d >> 2) & 1;
        sQf[((w*8+ks)*32 + g8*4 + tt)*4 + r + 2*hi] = f2tf(qg[idx] * 0.03125f);
    }

    float m2[2] = {-INFINITY, -INFINITY};
    float l2[2] = {0.f, 0.f};
    float o[8][4];
    #pragma unroll
    for (int nt = 0; nt < 8; ++nt) { o[nt][0]=o[nt][1]=o[nt][2]=o[nt][3]=0.f; }

    #pragma unroll 1
    for (int kt = 0; kt < 16; ++kt) {
        __syncthreads();
        const float* kgt = kg + kt*4096;
        const float* vgt = vg + kt*4096;
        for (int idx = tid; idx < 4096; idx += 256) {
            const int j = idx >> 6, d = idx & 63;
            {   // K: n-dim = j, k-dim = d
                const int nt = j >> 3, g8 = j & 7;
                const int ks = d >> 3, tt = d & 3, hi = (d >> 2) & 1;
                sKf[((nt*8+ks)*32 + g8*4 + tt)*2 + hi] = f2tf(kgt[idx]);
            }
            {   // V: k-dim = j, n-dim = d
                const int ks = j >> 3, tt = j & 3, hi = (j >> 2) & 1;
                const int dt = d >> 3, g8 = d & 7;
                sVf[((ks*8+dt)*32 + g8*4 + tt)*2 + hi] = f2tf(vgt[idx]);
            }
        }
        __syncthreads();

        // ---- scores = Q K^T ----
        float sc[8][4];
        #pragma unroll
        for (int nt = 0; nt < 8; ++nt) { sc[nt][0]=sc[nt][1]=sc[nt][2]=sc[nt][3]=0.f; }

        #pragma unroll
        for (int ks = 0; ks < 8; ++ks) {
            const float4 av = *(const float4*)&sQf[((wid*8+ks)*32 + lane)*4];
            #pragma unroll
            for (int nt = 0; nt < 8; ++nt) {
                const float2 bb = *(const float2*)&sKf[((nt*8+ks)*32 + lane)*2];
                mma8(sc[nt], (const float*)&av, (const float*)&bb);
            }
        }

        // ---- online softmax (quad owns a row) ----
        #pragma unroll
        for (int r = 0; r < 2; ++r) {
            const int row = rA + 8*r;
            float mt = -INFINITY;
            #pragma unroll
            for (int nt = 0; nt < 8; ++nt)
                mt = fmaxf(mt, fmaxf(sc[nt][2*r], sc[nt][2*r+1]));
            mt = fmaxf(mt, __shfl_xor_sync(0xffffffffu, mt, 1));
            mt = fmaxf(mt, __shfl_xor_sync(0xffffffffu, mt, 2));
            const float mn = fmaxf(m2[r], mt);
            const float corr = __expf(m2[r] - mn);
            float ssum = 0.f;
            #pragma unroll
            for (int nt = 0; nt < 8; ++nt) {
                const float p0 = __expf(sc[nt][2*r]   - mn);
                const float p1 = __expf(sc[nt][2*r+1] - mn);
                ssum += p0 + p1;
                *(float2*)&sP[row*PADP + nt*8 + t4*2] = make_float2(f2tf(p0), f2tf(p1));
            }
            ssum += __shfl_xor_sync(0xffffffffu, ssum, 1);
            ssum += __shfl_xor_sync(0xffffffffu, ssum, 2);
            l2[r] = l2[r]*corr + ssum;
            m2[r] = mn;
            #pragma unroll
            for (int nt = 0; nt < 8; ++nt) { o[nt][2*r] *= corr; o[nt][2*r+1] *= corr; }
        }
        __syncwarp();

        // ---- O += P V ----
        #pragma unroll
        for (int ks = 0; ks < 8; ++ks) {
            const int ac = ks*8 + t4;
            float a[4];
            a[0] = sP[rA*PADP + ac];
            a[1] = sP[(rA+8)*PADP + ac];
            a[2] = sP[rA*PADP + ac + 4];
            a[3] = sP[(rA+8)*PADP + ac + 4];
            #pragma unroll
            for (int dt = 0; dt < 8; ++dt) {
                const float2 bb = *(const float2*)&sVf[((ks*8+dt)*32 + lane)*2];
                mma8(o[dt], a, (const float*)&bb);
            }
        }
    }

    // ---- finalize: o/l + residual, stage, transposed store ----
    __syncthreads();
    {
        const float* xg = g_xh + (hb*NS + s0)*ND;
        #pragma unroll
        for (int r = 0; r < 2; ++r) {
            const float inv = 1.0f / l2[r];
            const int row = rA + 8*r;
            #pragma unroll
            for (int dt = 0; dt < 8; ++dt) {
                const int col = dt*8 + t4*2;
                const float2 xr = *(const float2*)&xg[row*64 + col];
                *(float2*)&sP[row*PADP + col] =
                    make_float2(o[dt][2*r]*inv + xr.x, o[dt][2*r+1]*inv + xr.y);
            }
        }
    }
    __syncthreads();
    {
        float* yg = g_y + (size_t)b*NE*NS + (size_t)(h*64)*NS + s0;
        for (int idx = tid; idx < 64*128; idx += 256) {
            const int d = idx >> 7, si = idx & 127;
            yg[d*NS + si] = sP[si*PADP + d];
        }
    }
}

// ---------------- kernel 3: layernorm ----------------
__global__ __launch_bounds__(256) void k_ln(const float* __restrict__ gamma,
                                            const float* __restrict__ beta,
                                            float* __restrict__ out)
{
    __shared__ float rsum[8][33];
    __shared__ float rsq [8][33];
    __shared__ float smu[32], srs[32];
    const int tid = threadIdx.x;
    const int sl = tid & 31, eg = tid >> 5;
    const int b = blockIdx.y;
    const int s = blockIdx.x*32 + sl;
    const float* yb = g_y + (size_t)b*NE*NS + s;

    float sum = 0.f, sq = 0.f;
    #pragma unroll 4
    for (int e = eg; e < NE; e += 8) {
        const float v = yb[(size_t)e*NS];
        sum += v; sq += v*v;
    }
    rsum[eg][sl] = sum; rsq[eg][sl] = sq;
    __syncthreads();
    if (eg == 0) {
        float ts = 0.f, tq = 0.f;
        #pragma unroll
        for (int g = 0; g < 8; ++g) { ts += rsum[g][sl]; tq += rsq[g][sl]; }
        const float mu = ts * (1.0f/1024.0f);
        const float var = tq * (1.0f/1024.0f) - mu*mu;
        smu[sl] = mu; srs[sl] = rsqrtf(var + 1e-5f);
    }
    __syncthreads();
    const float mu = smu[sl], rs = srs[sl];
    float* ob = out + (size_t)b*NE*NS + s;
    #pragma unroll 4
    for (int e = eg; e < NE; e += 8) {
        const float v = yb[(size_t)e*NS];
        ob[(size_t)e*NS] = (v - mu)*rs*__ldg(&gamma[e]) + __ldg(&beta[e]);
    }
}

// ---------------- launcher ----------------
extern "C" void kernel_launch(void* const* d_in, const int* in_sizes, int n_in,
                              void* d_out, int out_size)
{
    (void)in_sizes; (void)n_in; (void)out_size;
    const float* x   = (const float*)d_in[0];
    const float* Wq1 = (const float*)d_in[1];  const float* bq1 = (const float*)d_in[2];
    const float* Wq2 = (const float*)d_in[3];  const float* bq2 = (const float*)d_in[4];
    const float* Wk1 = (const float*)d_in[5];  const float* bk1 = (const float*)d_in[6];
    const float* Wk2 = (const float*)d_in[7];  const float* bk2 = (const float*)d_in[8];
    const float* Wv1 = (const float*)d_in[9];  const float* bv1 = (const float*)d_in[10];
    const float* Wv2 = (const float*)d_in[11]; const float* bv2 = (const float*)d_in[12];
    const float* gamma = (const float*)d_in[13];
    const float* beta  = (const float*)d_in[14];
    float* out = (float*)d_out;

    const int smem1 = SMEM1_FLOATS * (int)sizeof(float);
    const int smem2 = SMEM2_FLOATS * (int)sizeof(float);
    cudaFuncSetAttribute(k_qkv,  cudaFuncAttributeMaxDynamicSharedMemorySize, smem1);
    cudaFuncSetAttribute(k_attn, cudaFuncAttributeMaxDynamicSharedMemorySize, smem2);

    dim3 g1(NS/128, NB, NH);
    k_qkv<<<g1, 256, smem1>>>(x, Wq1, bq1, Wq2, bq2, Wk1, bk1, Wk2, bk2, Wv1, bv1, Wv2, bv2);

    dim3 g2(NS/128, NB, NH);
    k_attn<<<g2, 256, smem2>>>();

    dim3 g3(NS/32, NB);
    k_ln<<<g3, 256>>>(gamma, beta, out);
}

// round 6
// speedup vs baseline: 2.8057x; 1.5762x over previous
#include <cuda_runtime.h>
#include <math.h>
#include <stdint.h>

#define NB 8
#define NH 16
#define ND 64
#define NS 1024
#define NE 1024
#define PADP 68   // row stride: 68 % 32 == 4 -> conflict-free row-set accesses

// ---------------- scratch ----------------
__device__ float g_xh[NH*NB*NS*ND];  // (h,b,s,d) pos-encoded input (residual), fp32
__device__ float g_q [NH*NB*NS*ND];  // tf32, A-frag layout per 128-row tile, scale folded
__device__ float g_k [NH*NB*NS*ND];  // tf32, B-frag layout per 64-row chunk
__device__ float g_v [NH*NB*NS*ND];  // tf32, B-frag (V role) layout per 64-row chunk
__device__ float g_y [NB*NE*NS];     // (b,e,s) pre-layernorm

// ---------------- helpers ----------------
__device__ __forceinline__ float f2tf(float x) {
    uint32_t r;
    asm("cvt.rna.tf32.f32 %0, %1;" : "=r"(r) : "f"(x));
    return __uint_as_float(r);
}
__device__ __forceinline__ float ftanh(float x) {
    const float e = __expf(2.0f * x);
    return 1.0f - __fdividef(2.0f, e + 1.0f);
}
__device__ __forceinline__ void mma8(float* c, const float* a, const float* b) {
    asm volatile(
        "mma.sync.aligned.m16n8k8.row.col.f32.tf32.tf32.f32 "
        "{%0,%1,%2,%3}, {%4,%5,%6,%7}, {%8,%9}, {%0,%1,%2,%3};\n"
        : "+f"(c[0]), "+f"(c[1]), "+f"(c[2]), "+f"(c[3])
        : "r"(__float_as_uint(a[0])), "r"(__float_as_uint(a[1])),
          "r"(__float_as_uint(a[2])), "r"(__float_as_uint(a[3])),
          "r"(__float_as_uint(b[0])), "r"(__float_as_uint(b[1])));
}
__device__ __forceinline__ uint32_t su(const void* p) {
    return (uint32_t)__cvta_generic_to_shared(p);
}
__device__ __forceinline__ void cp16(uint32_t s, const void* g) {
    asm volatile("cp.async.cg.shared.global [%0], [%1], 16;\n" :: "r"(s), "l"(g));
}
#define CP_COMMIT asm volatile("cp.async.commit_group;\n" ::: "memory")
#define CP_WAIT0  asm volatile("cp.async.wait_group 0;\n" ::: "memory")
#define CP_WAIT1  asm volatile("cp.async.wait_group 1;\n" ::: "memory")

// Fragment layouts (lane = gid*4 + t4):
//  A-frag (128x64): af[((w*8+ks)*32 + lane)*4 + (r + 2*hi)] = A[w*16+gid+8r][ks*8+t4+4hi]
//  B-frag (64n x 64k): bf[((nt*8+ks)*32 + lane)*2 + hi]     = Bn[nt*8+gid][ks*8+t4+4hi]
//  V-frag (k=j, n=d):  vf[((ks*8+dt)*32 + lane)*2 + hi]     = V[ks*8+4hi+t4][dt*8+gid]

// ---------------- kernel 1: posenc + QKV MLPs ----------------
// smem: sXHf[8192] | sZ[128*68] | sWf[4096] | sWraw[4096]  = 98KB
#define SMEM1_FLOATS (8192 + 128*PADP + 4096 + 4096)

__device__ __forceinline__ void qkv_l1(const float* __restrict__ sXHf,
                                       const float* __restrict__ sWf,
                                       const float* __restrict__ biasg,
                                       float* __restrict__ sZ,
                                       int wid, int lane, int gid, int t4)
{
    const int rA = wid*16 + gid;
    float cc[8][4];
    #pragma unroll
    for (int nt = 0; nt < 8; ++nt) { cc[nt][0]=cc[nt][1]=cc[nt][2]=cc[nt][3]=0.f; }
    #pragma unroll
    for (int ks = 0; ks < 8; ++ks) {
        const float4 av = *(const float4*)&sXHf[((wid*8+ks)*32 + lane)*4];
        #pragma unroll
        for (int nt = 0; nt < 8; ++nt) {
            const float2 bb = *(const float2*)&sWf[((nt*8+ks)*32 + lane)*2];
            mma8(cc[nt], (const float*)&av, (const float*)&bb);
        }
    }
    __syncwarp();
    #pragma unroll
    for (int nt = 0; nt < 8; ++nt) {
        const float2 bv = *(const float2*)&biasg[nt*8 + t4*2];
        #pragma unroll
        for (int r = 0; r < 2; ++r) {
            const int row = rA + 8*r;
            *(float2*)&sZ[row*PADP + nt*8 + t4*2] =
                make_float2(f2tf(ftanh(cc[nt][2*r] + bv.x)),
                            f2tf(ftanh(cc[nt][2*r+1] + bv.y)));
        }
    }
}

__device__ __forceinline__ void qkv_l2(float* __restrict__ sZ,
                                       const float* __restrict__ sWf,
                                       const float* __restrict__ biasg,
                                       int wid, int lane, int gid, int t4)
{
    const int rA = wid*16 + gid;
    float cc[8][4];
    #pragma unroll
    for (int nt = 0; nt < 8; ++nt) { cc[nt][0]=cc[nt][1]=cc[nt][2]=cc[nt][3]=0.f; }
    #pragma unroll
    for (int ks = 0; ks < 8; ++ks) {
        const int ac = ks*8 + t4;
        float a[4];
        a[0] = sZ[rA*PADP + ac];
        a[1] = sZ[(rA+8)*PADP + ac];
        a[2] = sZ[rA*PADP + ac + 4];
        a[3] = sZ[(rA+8)*PADP + ac + 4];
        #pragma unroll
        for (int nt = 0; nt < 8; ++nt) {
            const float2 bb = *(const float2*)&sWf[((nt*8+ks)*32 + lane)*2];
            mma8(cc[nt], a, (const float*)&bb);
        }
    }
    __syncwarp();   // all A-reads of this warp's rows done before overwrite
    #pragma unroll
    for (int nt = 0; nt < 8; ++nt) {
        const float2 bv = *(const float2*)&biasg[nt*8 + t4*2];
        #pragma unroll
        for (int r = 0; r < 2; ++r) {
            const int row = rA + 8*r;
            *(float2*)&sZ[row*PADP + nt*8 + t4*2] =
                make_float2(ftanh(cc[nt][2*r] + bv.x),
                            ftanh(cc[nt][2*r+1] + bv.y));
        }
    }
}

__global__ __launch_bounds__(256, 2) void k_qkv(
    const float* __restrict__ x,
    const float* __restrict__ Wq1, const float* __restrict__ bq1,
    const float* __restrict__ Wq2, const float* __restrict__ bq2,
    const float* __restrict__ Wk1, const float* __restrict__ bk1,
    const float* __restrict__ Wk2, const float* __restrict__ bk2,
    const float* __restrict__ Wv1, const float* __restrict__ bv1,
    const float* __restrict__ Wv2, const float* __restrict__ bv2)
{
    extern __shared__ float sm[];
    float* sXHf  = sm;                       // [8192]
    float* sZ    = sXHf + 8192;              // [128*68]
    float* sWf   = sZ + 128*PADP;            // [4096]
    float* sWraw = sWf + 4096;               // [4096]
    const uint32_t sWraw_u = su(sWraw);

    const int tid = threadIdx.x;
    const int lane = tid & 31, wid = tid >> 5;
    const int gid = lane >> 2, t4 = lane & 3;
    const int h = blockIdx.z, b = blockIdx.y, bx = blockIdx.x;
    const int s0 = bx * 128;
    const int hb = h*NB + b;

    // xh = x + posenc (exact fp32) -> sZ
    for (int idx = tid; idx < 128*64; idx += 256) {
        const int d = idx >> 7, si = idx & 127;
        const int s = s0 + si;
        const float xv = x[(b*NE + (h*64 + d))*NS + s];
        const int l = h*64 + (s >> 4);
        const int e = ((s & 15) << 6) | d;
        const float freq = expf((float)(e >> 1) * (-2.0f*9.210340371976184f/1024.0f));
        const float ang = (float)l * freq;
        const float pe = (e & 1) ? cosf(ang) : sinf(ang);
        sZ[si*PADP + d] = xv + pe;
    }
    __syncthreads();
    {   // residual persist + xh A-frag build
        float* dst = g_xh + (hb*NS + s0)*ND;
        for (int idx = tid; idx < 128*16; idx += 256) {
            const int si = idx >> 4, d4 = (idx & 15) * 4;
            *(float4*)(dst + si*64 + d4) = *(float4*)&sZ[si*PADP + d4];
        }
        for (int idx = tid; idx < 128*64; idx += 256) {
            const int si = idx >> 6, d = idx & 63;
            const int w = si >> 4, g8 = si & 7, r = (si >> 3) & 1;
            const int ks = d >> 3, tt = d & 3, hi = (d >> 2) & 1;
            sXHf[((w*8+ks)*32 + g8*4 + tt)*4 + r + 2*hi] = f2tf(sZ[si*PADP + d]);
        }
    }

    const float* Wl[6] = {Wq1, Wq2, Wk1, Wk2, Wv1, Wv2};
    const float* Bl[6] = {bq1, bq2, bk1, bk2, bv1, bv2};
    float* outs[3] = {g_q, g_k, g_v};

    // prefetch W0
    {
        const float* src = Wl[0] + h*4096;
        #pragma unroll
        for (int i = 0; i < 4; ++i)
            cp16(sWraw_u + (tid + i*256)*16, src + (tid + i*256)*4);
        CP_COMMIT;
    }
    CP_WAIT0;
    __syncthreads();
    for (int idx = tid; idx < 4096; idx += 256) {   // raw -> B-frag (rounded)
        const int d = idx >> 6, e = idx & 63;
        const int nt = e >> 3, g8 = e & 7;
        const int ks = d >> 3, tt = d & 3, hi = (d >> 2) & 1;
        sWf[((nt*8+ks)*32 + g8*4 + tt)*2 + hi] = f2tf(sWraw[idx]);
    }
    __syncthreads();

    for (int l = 0; l < 6; ++l) {
        if (l < 5) {   // prefetch next W, overlapped with compute
            const float* src = Wl[l+1] + h*4096;
            #pragma unroll
            for (int i = 0; i < 4; ++i)
                cp16(sWraw_u + (tid + i*256)*16, src + (tid + i*256)*4);
            CP_COMMIT;
        }
        const int p = l >> 1;
        if ((l & 1) == 0) {
            qkv_l1(sXHf, sWf, Bl[l] + h*64, sZ, wid, lane, gid, t4);
            __syncthreads();
        } else {
            qkv_l2(sZ, sWf, Bl[l] + h*64, wid, lane, gid, t4);
            __syncthreads();
            // permute sZ -> global fragment layout
            if (p == 0) {   // Q: A-frag per 128-row tile, scale folded
                float* qb = g_q + (hb*8 + bx)*8192;
                for (int fi = tid; fi < 8192; fi += 256) {
                    const int rhi = fi & 3, r = rhi & 1, hi = rhi >> 1;
                    const int ln = (fi >> 2) & 31, g8 = ln >> 2, tt = ln & 3;
                    const int ks = (fi >> 7) & 7, w = fi >> 10;
                    const int row = w*16 + g8 + 8*r;
                    const int col = ks*8 + tt + 4*hi;
                    qb[fi] = f2tf(0.03125f * sZ[row*PADP + col]);
                }
            } else if (p == 1) {  // K: B-frag per 64-row chunk
                float* kb = g_k + (hb*16 + bx*2)*4096;
                for (int idx = tid; idx < 8192; idx += 256) {
                    const int cl = idx >> 12, f = idx & 4095;
                    const int hi = f & 1;
                    const int ln = (f >> 1) & 31, g8 = ln >> 2, tt = ln & 3;
                    const int ks = (f >> 6) & 7, nt = f >> 9;
                    const int si = cl*64 + nt*8 + g8;
                    const int col = ks*8 + tt + 4*hi;
                    kb[cl*4096 + f] = f2tf(sZ[si*PADP + col]);
                }
            } else {              // V: k=j, n=d frag per 64-row chunk
                float* vb = g_v + (hb*16 + bx*2)*4096;
                for (int idx = tid; idx < 8192; idx += 256) {
                    const int cl = idx >> 12, f = idx & 4095;
                    const int hi = f & 1;
                    const int ln = (f >> 1) & 31, g8 = ln >> 2, tt = ln & 3;
                    const int dt = (f >> 6) & 7, ksv = f >> 9;
                    const int si = cl*64 + ksv*8 + 4*hi + tt;
                    const int col = dt*8 + g8;
                    vb[cl*4096 + f] = f2tf(sZ[si*PADP + col]);
                }
            }
        }
        if (l < 5) {
            CP_WAIT0;
            __syncthreads();
            for (int idx = tid; idx < 4096; idx += 256) {
                const int d = idx >> 6, e = idx & 63;
                const int nt = e >> 3, g8 = e & 7;
                const int ks = d >> 3, tt = d & 3, hi = (d >> 2) & 1;
                sWf[((nt*8+ks)*32 + g8*4 + tt)*2 + hi] = f2tf(sWraw[idx]);
            }
            __syncthreads();
        }
    }
    (void)outs;
}

// ---------------- kernel 2: flash attention (frag-streamed, cp.async 2-stage) ----
// smem: sQf[8192] | buf0 K/V [8192] | buf1 K/V [8192] = 96KB
#define SMEM2_FLOATS (8192 + 8192 + 8192)

__global__ __launch_bounds__(256, 2) void k_attn()
{
    extern __shared__ float sm[];
    float* sQf = sm;                  // [8192] Q A-frag (tf32, scaled) - from g_q raw
    float* buf0 = sm + 8192;          // K frag [4096] + V frag [4096]
    float* buf1 = sm + 16384;
    const uint32_t b0u = su(buf0), b1u = su(buf1), qfu = su(sQf);

    const int tid = threadIdx.x;
    const int lane = tid & 31, wid = tid >> 5;
    const int gid = lane >> 2, t4 = lane & 3;
    const int rA = wid*16 + gid;

    const int h = blockIdx.z, b = blockIdx.y, bx = blockIdx.x;
    const int hb = h*NB + b;
    const float* qt = g_q + (hb*8 + bx)*8192;
    const float* kb = g_k + hb*16*4096;
    const float* vb = g_v + hb*16*4096;

    // group0: Q + chunk0 ; group1: chunk1
    #pragma unroll
    for (int i = 0; i < 8; ++i)
        cp16(qfu + (tid + i*256)*16, qt + (tid + i*256)*4);
    #pragma unroll
    for (int i = 0; i < 4; ++i) {
        cp16(b0u + (tid + i*256)*16,        kb + (tid + i*256)*4);
        cp16(b0u + 16384 + (tid + i*256)*16, vb + (tid + i*256)*4);
    }
    CP_COMMIT;
    #pragma unroll
    for (int i = 0; i < 4; ++i) {
        cp16(b1u + (tid + i*256)*16,        kb + 4096 + (tid + i*256)*4);
        cp16(b1u + 16384 + (tid + i*256)*16, vb + 4096 + (tid + i*256)*4);
    }
    CP_COMMIT;

    float m2[2] = {-INFINITY, -INFINITY};
    float l2[2] = {0.f, 0.f};
    float o[8][4];
    #pragma unroll
    for (int nt = 0; nt < 8; ++nt) { o[nt][0]=o[nt][1]=o[nt][2]=o[nt][3]=0.f; }

    const int qsrc1 = (lane & ~3) | (t4 >> 1);
    const int qsrc2 = qsrc1 + 2;
    const bool osel = (t4 & 1);

    #pragma unroll 1
    for (int kt = 0; kt < 16; ++kt) {
        if (kt < 15) { CP_WAIT1; } else { CP_WAIT0; }
        __syncthreads();
        const float* Kf = (kt & 1) ? buf1 : buf0;
        const float* Vf = Kf + 4096;

        // ---- scores = Q K^T ----
        float sc[8][4];
        #pragma unroll
        for (int nt = 0; nt < 8; ++nt) { sc[nt][0]=sc[nt][1]=sc[nt][2]=sc[nt][3]=0.f; }
        #pragma unroll
        for (int ks = 0; ks < 8; ++ks) {
            const float4 av = *(const float4*)&sQf[((wid*8+ks)*32 + lane)*4];
            #pragma unroll
            for (int nt = 0; nt < 8; ++nt) {
                const float2 bb = *(const float2*)&Kf[((nt*8+ks)*32 + lane)*2];
                mma8(sc[nt], (const float*)&av, (const float*)&bb);
            }
        }

        // ---- online softmax; exp values overwrite sc ----
        #pragma unroll
        for (int r = 0; r < 2; ++r) {
            float mt = -INFINITY;
            #pragma unroll
            for (int nt = 0; nt < 8; ++nt)
                mt = fmaxf(mt, fmaxf(sc[nt][2*r], sc[nt][2*r+1]));
            mt = fmaxf(mt, __shfl_xor_sync(0xffffffffu, mt, 1));
            mt = fmaxf(mt, __shfl_xor_sync(0xffffffffu, mt, 2));
            const float mn = fmaxf(m2[r], mt);
            const float corr = __expf(m2[r] - mn);
            float ssum = 0.f;
            #pragma unroll
            for (int nt = 0; nt < 8; ++nt) {
                const float p0 = __expf(sc[nt][2*r]   - mn);
                const float p1 = __expf(sc[nt][2*r+1] - mn);
                sc[nt][2*r] = p0; sc[nt][2*r+1] = p1;
                ssum += p0 + p1;
            }
            ssum += __shfl_xor_sync(0xffffffffu, ssum, 1);
            ssum += __shfl_xor_sync(0xffffffffu, ssum, 2);
            l2[r] = l2[r]*corr + ssum;
            m2[r] = mn;
            #pragma unroll
            for (int nt = 0; nt < 8; ++nt) { o[nt][2*r] *= corr; o[nt][2*r+1] *= corr; }
        }

        // ---- O += P V : P A-frag via intra-quad shuffles ----
        #pragma unroll
        for (int ks = 0; ks < 8; ++ks) {
            const float x0 = __shfl_sync(0xffffffffu, sc[ks][0], qsrc1);
            const float x1 = __shfl_sync(0xffffffffu, sc[ks][1], qsrc1);
            const float x2 = __shfl_sync(0xffffffffu, sc[ks][2], qsrc1);
            const float x3 = __shfl_sync(0xffffffffu, sc[ks][3], qsrc1);
            const float y0 = __shfl_sync(0xffffffffu, sc[ks][0], qsrc2);
            const float y1 = __shfl_sync(0xffffffffu, sc[ks][1], qsrc2);
            const float y2 = __shfl_sync(0xffffffffu, sc[ks][2], qsrc2);
            const float y3 = __shfl_sync(0xffffffffu, sc[ks][3], qsrc2);
            float a[4];
            a[0] = osel ? x1 : x0;   // P(rA,   ks*8+t4)
            a[1] = osel ? x3 : x2;   // P(rA+8, ks*8+t4)
            a[2] = osel ? y1 : y0;   // P(rA,   ks*8+t4+4)
            a[3] = osel ? y3 : y2;   // P(rA+8, ks*8+t4+4)
            #pragma unroll
            for (int dt = 0; dt < 8; ++dt) {
                const float2 bb = *(const float2*)&Vf[((ks*8+dt)*32 + lane)*2];
                mma8(o[dt], a, (const float*)&bb);
            }
        }
        __syncthreads();
        if (kt + 2 < 16) {
            const uint32_t bu = (kt & 1) ? b1u : b0u;
            const float* ks_ = kb + (kt+2)*4096;
            const float* vs_ = vb + (kt+2)*4096;
            #pragma unroll
            for (int i = 0; i < 4; ++i) {
                cp16(bu + (tid + i*256)*16,         ks_ + (tid + i*256)*4);
                cp16(bu + 16384 + (tid + i*256)*16, vs_ + (tid + i*256)*4);
            }
            CP_COMMIT;
        }
    }

    // ---- finalize: o/l + residual, stage (reuse buffer area), transposed store ----
    float* sO = sm + 8192;   // [128*68] fits in 16384
    {
        const float* xg = g_xh + (hb*NS + bx*128)*ND;
        #pragma unroll
        for (int r = 0; r < 2; ++r) {
            const float inv = 1.0f / l2[r];
            const int row = rA + 8*r;
            #pragma unroll
            for (int dt = 0; dt < 8; ++dt) {
                const int col = dt*8 + t4*2;
                const float2 xr = *(const float2*)&xg[row*64 + col];
                *(float2*)&sO[row*PADP + col] =
                    make_float2(o[dt][2*r]*inv + xr.x, o[dt][2*r+1]*inv + xr.y);
            }
        }
    }
    __syncthreads();
    {
        float* yg = g_y + (size_t)b*NE*NS + (size_t)(h*64)*NS + bx*128;
        for (int idx = tid; idx < 64*128; idx += 256) {
            const int d = idx >> 7, si = idx & 127;
            yg[d*NS + si] = sO[si*PADP + d];
        }
    }
}

// ---------------- kernel 3: layernorm ----------------
__global__ __launch_bounds__(256) void k_ln(const float* __restrict__ gamma,
                                            const float* __restrict__ beta,
                                            float* __restrict__ out)
{
    __shared__ float rsum[8][33];
    __shared__ float rsq [8][33];
    __shared__ float smu[32], srs[32];
    const int tid = threadIdx.x;
    const int sl = tid & 31, eg = tid >> 5;
    const int b = blockIdx.y;
    const int s = blockIdx.x*32 + sl;
    const float* yb = g_y + (size_t)b*NE*NS + s;

    float sum = 0.f, sq = 0.f;
    #pragma unroll 4
    for (int e = eg; e < NE; e += 8) {
        const float v = yb[(size_t)e*NS];
        sum += v; sq += v*v;
    }
    rsum[eg][sl] = sum; rsq[eg][sl] = sq;
    __syncthreads();
    if (eg == 0) {
        float ts = 0.f, tq = 0.f;
        #pragma unroll
        for (int g = 0; g < 8; ++g) { ts += rsum[g][sl]; tq += rsq[g][sl]; }
        const float mu = ts * (1.0f/1024.0f);
        const float var = tq * (1.0f/1024.0f) - mu*mu;
        smu[sl] = mu; srs[sl] = rsqrtf(var + 1e-5f);
    }
    __syncthreads();
    const float mu = smu[sl], rs = srs[sl];
    float* ob = out + (size_t)b*NE*NS + s;
    #pragma unroll 4
    for (int e = eg; e < NE; e += 8) {
        const float v = yb[(size_t)e*NS];
        ob[(size_t)e*NS] = (v - mu)*rs*__ldg(&gamma[e]) + __ldg(&beta[e]);
    }
}

// ---------------- launcher ----------------
extern "C" void kernel_launch(void* const* d_in, const int* in_sizes, int n_in,
                              void* d_out, int out_size)
{
    (void)in_sizes; (void)n_in; (void)out_size;
    const float* x   = (const float*)d_in[0];
    const float* Wq1 = (const float*)d_in[1];  const float* bq1 = (const float*)d_in[2];
    const float* Wq2 = (const float*)d_in[3];  const float* bq2 = (const float*)d_in[4];
    const float* Wk1 = (const float*)d_in[5];  const float* bk1 = (const float*)d_in[6];
    const float* Wk2 = (const float*)d_in[7];  const float* bk2 = (const float*)d_in[8];
    const float* Wv1 = (const float*)d_in[9];  const float* bv1 = (const float*)d_in[10];
    const float* Wv2 = (const float*)d_in[11]; const float* bv2 = (const float*)d_in[12];
    const float* gamma = (const float*)d_in[13];
    const float* beta  = (const float*)d_in[14];
    float* out = (float*)d_out;

    const int smem1 = SMEM1_FLOATS * (int)sizeof(float);
    const int smem2 = SMEM2_FLOATS * (int)sizeof(float);
    cudaFuncSetAttribute(k_qkv,  cudaFuncAttributeMaxDynamicSharedMemorySize, smem1);
    cudaFuncSetAttribute(k_attn, cudaFuncAttributeMaxDynamicSharedMemorySize, smem2);

    dim3 g1(NS/128, NB, NH);
    k_qkv<<<g1, 256, smem1>>>(x, Wq1, bq1, Wq2, bq2, Wk1, bk1, Wk2, bk2, Wv1, bv1, Wv2, bv2);

    dim3 g2(NS/128, NB, NH);
    k_attn<<<g2, 256, smem2>>>();

    dim3 g3(NS/32, NB);
    k_ln<<<g3, 256>>>(gamma, beta, out);
}

// round 7
// speedup vs baseline: 3.1531x; 1.1238x over previous
#include <cuda_runtime.h>
#include <math.h>
#include <stdint.h>

#define NB 8
#define NH 16
#define ND 64
#define NS 1024
#define NE 1024
#define PADP 68   // row stride: 68 % 32 == 4 -> conflict-free row-set accesses

// ---------------- scratch ----------------
__device__ float g_pe[NH*ND*NS];     // (h,d,s) positional encoding
__device__ float g_xh[NH*NB*NS*ND];  // (h,b,s,d) pos-encoded input (residual), fp32
__device__ float g_q [NH*NB*NS*ND];  // A-frag layout per 128-row tile, scale folded
__device__ float g_k [NH*NB*NS*ND];  // B-frag layout per 64-row chunk
__device__ float g_v [NH*NB*NS*ND];  // B-frag (V role) layout per 64-row chunk
__device__ float g_y [NB*NE*NS];     // (b,e,s) pre-layernorm

// ---------------- helpers ----------------
__device__ __forceinline__ float ftanh(float x) {
    const float e = __expf(2.0f * x);
    return 1.0f - __fdividef(2.0f, e + 1.0f);
}
__device__ __forceinline__ void mma8(float* c, const float* a, const float* b) {
    asm volatile(
        "mma.sync.aligned.m16n8k8.row.col.f32.tf32.tf32.f32 "
        "{%0,%1,%2,%3}, {%4,%5,%6,%7}, {%8,%9}, {%0,%1,%2,%3};\n"
        : "+f"(c[0]), "+f"(c[1]), "+f"(c[2]), "+f"(c[3])
        : "r"(__float_as_uint(a[0])), "r"(__float_as_uint(a[1])),
          "r"(__float_as_uint(a[2])), "r"(__float_as_uint(a[3])),
          "r"(__float_as_uint(b[0])), "r"(__float_as_uint(b[1])));
}
__device__ __forceinline__ uint32_t su(const void* p) {
    return (uint32_t)__cvta_generic_to_shared(p);
}
__device__ __forceinline__ void cp16(uint32_t s, const void* g) {
    asm volatile("cp.async.cg.shared.global [%0], [%1], 16;\n" :: "r"(s), "l"(g));
}
__device__ __forceinline__ void cp4(uint32_t s, const void* g) {
    asm volatile("cp.async.ca.shared.global [%0], [%1], 4;\n" :: "r"(s), "l"(g));
}
#define CP_COMMIT asm volatile("cp.async.commit_group;\n" ::: "memory")
#define CP_WAIT0  asm volatile("cp.async.wait_group 0;\n" ::: "memory")

// Fragment layouts (lane = gid*4 + t4):
//  A-frag (128x64): af[((w*8+ks)*32 + lane)*4 + (r + 2*hi)] = A[w*16+gid+8r][ks*8+t4+4hi]
//  B-frag (64n x 64k): bf[((nt*8+ks)*32 + lane)*2 + hi]     = Bn[nt*8+gid][ks*8+t4+4hi]
//  V-frag (k=j, n=d):  vf[((ks*8+dt)*32 + lane)*2 + hi]     = V[ks*8+4hi+t4][dt*8+gid]

// ---------------- kernel 0: positional encoding table, (h,d,s) layout ----------------
__global__ __launch_bounds__(256) void k_pe()
{
    const int idx = blockIdx.x*256 + threadIdx.x;   // over NH*ND*NS
    const int h = idx >> 16, d = (idx >> 10) & 63, s = idx & 1023;
    const int l = h*64 + (s >> 4);
    const int e = ((s & 15) << 6) | d;
    const float freq = expf((float)(e >> 1) * (-2.0f*9.210340371976184f/1024.0f));
    const float ang = (float)l * freq;
    g_pe[idx] = (e & 1) ? cosf(ang) : sinf(ang);
}

// ---------------- kernel 1: posenc-add + QKV MLPs ----------------
// smem: sXHf[8192] | sZ[128*68] | sWf0[4096] | sWf1[4096] = 98KB
#define SMEM1_FLOATS (8192 + 128*PADP + 4096 + 4096)

__device__ __forceinline__ void wfetch(uint32_t dstu, const float* __restrict__ W, int tid)
{
    #pragma unroll
    for (int i = 0; i < 16; ++i) {
        const int fi = tid + i*256;
        const int hi = fi & 1, ln = (fi >> 1) & 31, ks = (fi >> 6) & 7, nt = fi >> 9;
        const int g8 = ln >> 2, tt = ln & 3;
        cp4(dstu + fi*4, W + (ks*8 + tt + 4*hi)*64 + nt*8 + g8);
    }
}

__device__ __forceinline__ void qkv_l1(const float* __restrict__ sXHf,
                                       const float* __restrict__ sWf,
                                       const float* __restrict__ biasg,
                                       float* __restrict__ sZ,
                                       int wid, int lane, int gid, int t4)
{
    const int rA = wid*16 + gid;
    float cc[8][4];
    #pragma unroll
    for (int nt = 0; nt < 8; ++nt) { cc[nt][0]=cc[nt][1]=cc[nt][2]=cc[nt][3]=0.f; }
    #pragma unroll
    for (int ks = 0; ks < 8; ++ks) {
        const float4 av = *(const float4*)&sXHf[((wid*8+ks)*32 + lane)*4];
        #pragma unroll
        for (int nt = 0; nt < 8; ++nt) {
            const float2 bb = *(const float2*)&sWf[((nt*8+ks)*32 + lane)*2];
            mma8(cc[nt], (const float*)&av, (const float*)&bb);
        }
    }
    #pragma unroll
    for (int nt = 0; nt < 8; ++nt) {
        const float2 bv = *(const float2*)&biasg[nt*8 + t4*2];
        #pragma unroll
        for (int r = 0; r < 2; ++r) {
            const int row = rA + 8*r;
            *(float2*)&sZ[row*PADP + nt*8 + t4*2] =
                make_float2(ftanh(cc[nt][2*r] + bv.x), ftanh(cc[nt][2*r+1] + bv.y));
        }
    }
    __syncwarp();   // lanes read cross-lane cols of these rows in l2
}

__device__ __forceinline__ void qkv_l2(float* __restrict__ sZ,
                                       const float* __restrict__ sWf,
                                       const float* __restrict__ biasg,
                                       int wid, int lane, int gid, int t4)
{
    const int rA = wid*16 + gid;
    float cc[8][4];
    #pragma unroll
    for (int nt = 0; nt < 8; ++nt) { cc[nt][0]=cc[nt][1]=cc[nt][2]=cc[nt][3]=0.f; }
    #pragma unroll
    for (int ks = 0; ks < 8; ++ks) {
        const int ac = ks*8 + t4;
        float a[4];
        a[0] = sZ[rA*PADP + ac];
        a[1] = sZ[(rA+8)*PADP + ac];
        a[2] = sZ[rA*PADP + ac + 4];
        a[3] = sZ[(rA+8)*PADP + ac + 4];
        #pragma unroll
        for (int nt = 0; nt < 8; ++nt) {
            const float2 bb = *(const float2*)&sWf[((nt*8+ks)*32 + lane)*2];
            mma8(cc[nt], a, (const float*)&bb);
        }
    }
    __syncwarp();   // all A-reads of this warp's rows done before overwrite
    #pragma unroll
    for (int nt = 0; nt < 8; ++nt) {
        const float2 bv = *(const float2*)&biasg[nt*8 + t4*2];
        #pragma unroll
        for (int r = 0; r < 2; ++r) {
            const int row = rA + 8*r;
            *(float2*)&sZ[row*PADP + nt*8 + t4*2] =
                make_float2(ftanh(cc[nt][2*r] + bv.x), ftanh(cc[nt][2*r+1] + bv.y));
        }
    }
}

__global__ __launch_bounds__(256, 2) void k_qkv(
    const float* __restrict__ x,
    const float* __restrict__ Wq1, const float* __restrict__ bq1,
    const float* __restrict__ Wq2, const float* __restrict__ bq2,
    const float* __restrict__ Wk1, const float* __restrict__ bk1,
    const float* __restrict__ Wk2, const float* __restrict__ bk2,
    const float* __restrict__ Wv1, const float* __restrict__ bv1,
    const float* __restrict__ Wv2, const float* __restrict__ bv2)
{
    extern __shared__ float sm[];
    float* sXHf = sm;                        // [8192]
    float* sZ   = sXHf + 8192;               // [128*68]
    float* sWfA = sZ + 128*PADP;             // [4096]
    float* sWfB = sWfA + 4096;               // [4096]

    const int tid = threadIdx.x;
    const int lane = tid & 31, wid = tid >> 5;
    const int gid = lane >> 2, t4 = lane & 3;
    const int h = blockIdx.z, b = blockIdx.y, bx = blockIdx.x;
    const int s0 = bx * 128;
    const int hb = h*NB + b;

    const float* Wl[6] = {Wq1, Wq2, Wk1, Wk2, Wv1, Wv2};
    const float* Bl[6] = {bq1, bq2, bk1, bk2, bv1, bv2};

    // prefetch W0 directly into frag layout; overlaps posenc work below
    wfetch(su(sWfA), Wl[0] + h*4096, tid);
    CP_COMMIT;

    // xh = x + pe (table lookup), into sZ
    for (int idx = tid; idx < 128*64; idx += 256) {
        const int d = idx >> 7, si = idx & 127;
        const int s = s0 + si;
        sZ[si*PADP + d] = x[(b*NE + (h*64 + d))*NS + s] + g_pe[h*65536 + (d << 10) + s];
    }
    __syncthreads();
    {   // residual persist + xh A-frag build
        float* dst = g_xh + (hb*NS + s0)*ND;
        for (int idx = tid; idx < 128*16; idx += 256) {
            const int si = idx >> 4, d4 = (idx & 15) * 4;
            *(float4*)(dst + si*64 + d4) = *(float4*)&sZ[si*PADP + d4];
        }
        for (int idx = tid; idx < 128*64; idx += 256) {
            const int si = idx >> 6, d = idx & 63;
            const int w = si >> 4, g8 = si & 7, r = (si >> 3) & 1;
            const int ks = d >> 3, tt = d & 3, hi = (d >> 2) & 1;
            sXHf[((w*8+ks)*32 + g8*4 + tt)*4 + r + 2*hi] = sZ[si*PADP + d];
        }
    }
    CP_WAIT0;
    __syncthreads();   // W0 visible; sXHf build complete before l1

    float* cur = sWfA;
    float* nxt = sWfB;

    #pragma unroll 1
    for (int l = 0; l < 6; ++l) {
        if (l < 5) { wfetch(su(nxt), Wl[l+1] + h*4096, tid); CP_COMMIT; }
        if ((l & 1) == 0) {
            qkv_l1(sXHf, cur, Bl[l] + h*64, sZ, wid, lane, gid, t4);
        } else {
            qkv_l2(sZ, cur, Bl[l] + h*64, wid, lane, gid, t4);
            __syncthreads();   // sZ final before block-wide permute reads
            const int p = l >> 1;
            if (p == 0) {          // Q: A-frag tiles, scale folded
                float* qb = g_q + (hb*8 + bx)*8192;
                for (int fi = tid; fi < 8192; fi += 256) {
                    const int rhi = fi & 3, r = rhi & 1, hi = rhi >> 1;
                    const int ln = (fi >> 2) & 31, g8 = ln >> 2, tt = ln & 3;
                    const int ks = (fi >> 7) & 7, w = fi >> 10;
                    qb[fi] = 0.03125f * sZ[(w*16 + g8 + 8*r)*PADP + ks*8 + tt + 4*hi];
                }
            } else if (p == 1) {   // K: B-frag chunks
                float* kb = g_k + (hb*16 + bx*2)*4096;
                for (int idx = tid; idx < 8192; idx += 256) {
                    const int cl = idx >> 12, f = idx & 4095;
                    const int hi = f & 1;
                    const int ln = (f >> 1) & 31, g8 = ln >> 2, tt = ln & 3;
                    const int ks = (f >> 6) & 7, nt = f >> 9;
                    kb[idx] = sZ[(cl*64 + nt*8 + g8)*PADP + ks*8 + tt + 4*hi];
                }
            } else {               // V: k=j, n=d frag chunks
                float* vb = g_v + (hb*16 + bx*2)*4096;
                for (int idx = tid; idx < 8192; idx += 256) {
                    const int cl = idx >> 12, f = idx & 4095;
                    const int hi = f & 1;
                    const int ln = (f >> 1) & 31, g8 = ln >> 2, tt = ln & 3;
                    const int dt = (f >> 6) & 7, ksv = f >> 9;
                    vb[idx] = sZ[(cl*64 + ksv*8 + 4*hi + tt)*PADP + dt*8 + g8];
                }
            }
        }
        if (l < 5) { CP_WAIT0; }
        __syncthreads();   // next W visible; sZ free for reuse
        float* t = cur; cur = nxt; nxt = t;
    }
}

// ---------------- kernel 2: flash attention (bounded-score softmax) ----------------
// smem: sQf[8192] | buf0 K/V [8192] | buf1 K/V [8192] = 96KB
#define SMEM2_FLOATS (8192 + 8192 + 8192)

__global__ __launch_bounds__(256, 2) void k_attn()
{
    extern __shared__ float sm[];
    float* sQf  = sm;
    float* buf0 = sm + 8192;
    float* buf1 = sm + 16384;
    const uint32_t b0u = su(buf0), b1u = su(buf1), qfu = su(sQf);

    const int tid = threadIdx.x;
    const int lane = tid & 31, wid = tid >> 5;
    const int gid = lane >> 2, t4 = lane & 3;
    const int rA = wid*16 + gid;

    const int h = blockIdx.z, b = blockIdx.y, bx = blockIdx.x;
    const int hb = h*NB + b;
    const float* qt = g_q + (hb*8 + bx)*8192;
    const float* kb = g_k + hb*16*4096;
    const float* vb = g_v + hb*16*4096;

    // group: Q + chunk0
    #pragma unroll
    for (int i = 0; i < 8; ++i)
        cp16(qfu + (tid + i*256)*16, qt + (tid + i*256)*4);
    #pragma unroll
    for (int i = 0; i < 4; ++i) {
        cp16(b0u + (tid + i*256)*16,         kb + (tid + i*256)*4);
        cp16(b0u + 16384 + (tid + i*256)*16, vb + (tid + i*256)*4);
    }
    CP_COMMIT;

    float l2[2] = {0.f, 0.f};
    float o[8][4];
    #pragma unroll
    for (int nt = 0; nt < 8; ++nt) { o[nt][0]=o[nt][1]=o[nt][2]=o[nt][3]=0.f; }

    const int qsrc1 = (lane & ~3) | (t4 >> 1);
    const int qsrc2 = qsrc1 + 2;
    const bool osel = (t4 & 1);

    #pragma unroll 1
    for (int kt = 0; kt < 16; ++kt) {
        CP_WAIT0;
        __syncthreads();   // chunk kt visible; everyone done with buffer being refilled
        if (kt < 15) {
            const uint32_t bu = ((kt+1) & 1) ? b1u : b0u;
            const float* ksrc = kb + (kt+1)*4096;
            const float* vsrc = vb + (kt+1)*4096;
            #pragma unroll
            for (int i = 0; i < 4; ++i) {
                cp16(bu + (tid + i*256)*16,         ksrc + (tid + i*256)*4);
                cp16(bu + 16384 + (tid + i*256)*16, vsrc + (tid + i*256)*4);
            }
            CP_COMMIT;
        }
        const float* Kf = (kt & 1) ? buf1 : buf0;
        const float* Vf = Kf + 4096;

        // ---- scores = Q K^T ----
        float sc[8][4];
        #pragma unroll
        for (int nt = 0; nt < 8; ++nt) { sc[nt][0]=sc[nt][1]=sc[nt][2]=sc[nt][3]=0.f; }
        #pragma unroll
        for (int ks = 0; ks < 8; ++ks) {
            const float4 av = *(const float4*)&sQf[((wid*8+ks)*32 + lane)*4];
            #pragma unroll
            for (int nt = 0; nt < 8; ++nt) {
                const float2 bb = *(const float2*)&Kf[((nt*8+ks)*32 + lane)*2];
                mma8(sc[nt], (const float*)&av, (const float*)&bb);
            }
        }

        // ---- softmax-lite: |score| <= 2 (tanh inputs), so no max tracking ----
        #pragma unroll
        for (int nt = 0; nt < 8; ++nt) {
            sc[nt][0] = __expf(sc[nt][0]);
            sc[nt][1] = __expf(sc[nt][1]);
            sc[nt][2] = __expf(sc[nt][2]);
            sc[nt][3] = __expf(sc[nt][3]);
            l2[0] += sc[nt][0] + sc[nt][1];
            l2[1] += sc[nt][2] + sc[nt][3];
        }

        // ---- O += P V : P A-frag via intra-quad shuffles ----
        #pragma unroll
        for (int ks = 0; ks < 8; ++ks) {
            const float x0 = __shfl_sync(0xffffffffu, sc[ks][0], qsrc1);
            const float x1 = __shfl_sync(0xffffffffu, sc[ks][1], qsrc1);
            const float x2 = __shfl_sync(0xffffffffu, sc[ks][2], qsrc1);
            const float x3 = __shfl_sync(0xffffffffu, sc[ks][3], qsrc1);
            const float y0 = __shfl_sync(0xffffffffu, sc[ks][0], qsrc2);
            const float y1 = __shfl_sync(0xffffffffu, sc[ks][1], qsrc2);
            const float y2 = __shfl_sync(0xffffffffu, sc[ks][2], qsrc2);
            const float y3 = __shfl_sync(0xffffffffu, sc[ks][3], qsrc2);
            float a[4];
            a[0] = osel ? x1 : x0;   // P(rA,   ks*8+t4)
            a[1] = osel ? x3 : x2;   // P(rA+8, ks*8+t4)
            a[2] = osel ? y1 : y0;   // P(rA,   ks*8+t4+4)
            a[3] = osel ? y3 : y2;   // P(rA+8, ks*8+t4+4)
            #pragma unroll
            for (int dt = 0; dt < 8; ++dt) {
                const float2 bb = *(const float2*)&Vf[((ks*8+dt)*32 + lane)*2];
                mma8(o[dt], a, (const float*)&bb);
            }
        }
    }

    // ---- finalize: reduce l, o/l + residual, stage, transposed store ----
    __syncthreads();   // all warps done reading buffers before reuse as sO
    l2[0] += __shfl_xor_sync(0xffffffffu, l2[0], 1);
    l2[0] += __shfl_xor_sync(0xffffffffu, l2[0], 2);
    l2[1] += __shfl_xor_sync(0xffffffffu, l2[1], 1);
    l2[1] += __shfl_xor_sync(0xffffffffu, l2[1], 2);

    float* sO = sm + 8192;   // [128*68] fits in 16384 floats
    {
        const float* xg = g_xh + (hb*NS + bx*128)*ND;
        #pragma unroll
        for (int r = 0; r < 2; ++r) {
            const float inv = 1.0f / l2[r];
            const int row = rA + 8*r;
            #pragma unroll
            for (int dt = 0; dt < 8; ++dt) {
                const int col = dt*8 + t4*2;
                const float2 xr = *(const float2*)&xg[row*64 + col];
                *(float2*)&sO[row*PADP + col] =
                    make_float2(o[dt][2*r]*inv + xr.x, o[dt][2*r+1]*inv + xr.y);
            }
        }
    }
    __syncthreads();
    {
        float* yg = g_y + (size_t)b*NE*NS + (size_t)(h*64)*NS + bx*128;
        for (int idx = tid; idx < 64*128; idx += 256) {
            const int d = idx >> 7, si = idx & 127;
            yg[d*NS + si] = sO[si*PADP + d];
        }
    }
}

// ---------------- kernel 3: layernorm ----------------
__global__ __launch_bounds__(256) void k_ln(const float* __restrict__ gamma,
                                            const float* __restrict__ beta,
                                            float* __restrict__ out)
{
    __shared__ float rsum[8][33];
    __shared__ float rsq [8][33];
    __shared__ float smu[32], srs[32];
    const int tid = threadIdx.x;
    const int sl = tid & 31, eg = tid >> 5;
    const int b = blockIdx.y;
    const int s = blockIdx.x*32 + sl;
    const float* yb = g_y + (size_t)b*NE*NS + s;

    float sum = 0.f, sq = 0.f;
    #pragma unroll 4
    for (int e = eg; e < NE; e += 8) {
        const float v = yb[(size_t)e*NS];
        sum += v; sq += v*v;
    }
    rsum[eg][sl] = sum; rsq[eg][sl] = sq;
    __syncthreads();
    if (eg == 0) {
        float ts = 0.f, tq = 0.f;
        #pragma unroll
        for (int g = 0; g < 8; ++g) { ts += rsum[g][sl]; tq += rsq[g][sl]; }
        const float mu = ts * (1.0f/1024.0f);
        const float var = tq * (1.0f/1024.0f) - mu*mu;
        smu[sl] = mu; srs[sl] = rsqrtf(var + 1e-5f);
    }
    __syncthreads();
    const float mu = smu[sl], rs = srs[sl];
    float* ob = out + (size_t)b*NE*NS + s;
    #pragma unroll 4
    for (int e = eg; e < NE; e += 8) {
        const float v = yb[(size_t)e*NS];
        ob[(size_t)e*NS] = (v - mu)*rs*__ldg(&gamma[e]) + __ldg(&beta[e]);
    }
}

// ---------------- launcher ----------------
extern "C" void kernel_launch(void* const* d_in, const int* in_sizes, int n_in,
                              void* d_out, int out_size)
{
    (void)in_sizes; (void)n_in; (void)out_size;
    const float* x   = (const float*)d_in[0];
    const float* Wq1 = (const float*)d_in[1];  const float* bq1 = (const float*)d_in[2];
    const float* Wq2 = (const float*)d_in[3];  const float* bq2 = (const float*)d_in[4];
    const float* Wk1 = (const float*)d_in[5];  const float* bk1 = (const float*)d_in[6];
    const float* Wk2 = (const float*)d_in[7];  const float* bk2 = (const float*)d_in[8];
    const float* Wv1 = (const float*)d_in[9];  const float* bv1 = (const float*)d_in[10];
    const float* Wv2 = (const float*)d_in[11]; const float* bv2 = (const float*)d_in[12];
    const float* gamma = (const float*)d_in[13];
    const float* beta  = (const float*)d_in[14];
    float* out = (float*)d_out;

    const int smem1 = SMEM1_FLOATS * (int)sizeof(float);
    const int smem2 = SMEM2_FLOATS * (int)sizeof(float);
    cudaFuncSetAttribute(k_qkv,  cudaFuncAttributeMaxDynamicSharedMemorySize, smem1);
    cudaFuncSetAttribute(k_attn, cudaFuncAttributeMaxDynamicSharedMemorySize, smem2);

    k_pe<<<NH*ND*NS/256, 256>>>();

    dim3 g1(NS/128, NB, NH);
    k_qkv<<<g1, 256, smem1>>>(x, Wq1, bq1, Wq2, bq2, Wk1, bk1, Wk2, bk2, Wv1, bv1, Wv2, bv2);

    dim3 g2(NS/128, NB, NH);
    k_attn<<<g2, 256, smem2>>>();

    dim3 g3(NS/32, NB);
    k_ln<<<g3, 256>>>(gamma, beta, out);
}

// round 8
// speedup vs baseline: 3.3976x; 1.0775x over previous
#include <cuda_runtime.h>
#include <math.h>
#include <stdint.h>

#define NB 8
#define NH 16
#define ND 64
#define NS 1024
#define NE 1024
#define PADP 68   // row stride: 68 % 32 == 4 -> conflict-free row-set accesses

// ---------------- scratch ----------------
__device__ float g_pe[NH*ND*NS];     // (h,d,s) positional encoding
__device__ float g_xh[NH*NB*NS*ND];  // (h,b,s,d) pos-encoded input (residual), fp32
__device__ float g_q [NH*NB*NS*ND];  // A-frag layout per 128-row tile, scale folded
__device__ float g_k [NH*NB*NS*ND];  // B-frag layout per 64-row chunk
__device__ float g_v [NH*NB*NS*ND];  // B-frag (V role) layout per 64-row chunk
__device__ float g_y [NB*NE*NS];     // (b,e,s) pre-layernorm
__device__ float g_psum[NH*NB*NS];   // per-head partial sum of y over its 64 dims
__device__ float g_psq [NH*NB*NS];   // per-head partial sum of y^2
__device__ float g_mu[NB*NS];        // layernorm mean
__device__ float g_rs[NB*NS];        // layernorm rsqrt(var+eps)

// ---------------- helpers ----------------
__device__ __forceinline__ float ftanh(float x) {
    const float e = __expf(2.0f * x);
    return 1.0f - __fdividef(2.0f, e + 1.0f);
}
__device__ __forceinline__ void mma8(float* c, const float* a, const float* b) {
    asm volatile(
        "mma.sync.aligned.m16n8k8.row.col.f32.tf32.tf32.f32 "
        "{%0,%1,%2,%3}, {%4,%5,%6,%7}, {%8,%9}, {%0,%1,%2,%3};\n"
        : "+f"(c[0]), "+f"(c[1]), "+f"(c[2]), "+f"(c[3])
        : "r"(__float_as_uint(a[0])), "r"(__float_as_uint(a[1])),
          "r"(__float_as_uint(a[2])), "r"(__float_as_uint(a[3])),
          "r"(__float_as_uint(b[0])), "r"(__float_as_uint(b[1])));
}
__device__ __forceinline__ uint32_t su(const void* p) {
    return (uint32_t)__cvta_generic_to_shared(p);
}
__device__ __forceinline__ void cp16(uint32_t s, const void* g) {
    asm volatile("cp.async.cg.shared.global [%0], [%1], 16;\n" :: "r"(s), "l"(g));
}
__device__ __forceinline__ void cp4(uint32_t s, const void* g) {
    asm volatile("cp.async.ca.shared.global [%0], [%1], 4;\n" :: "r"(s), "l"(g));
}
#define CP_COMMIT asm volatile("cp.async.commit_group;\n" ::: "memory")
#define CP_WAIT0  asm volatile("cp.async.wait_group 0;\n" ::: "memory")

// ---------------- kernel 0: positional encoding table, (h,d,s) layout ----------------
__global__ __launch_bounds__(256) void k_pe()
{
    const int idx = blockIdx.x*256 + threadIdx.x;   // over NH*ND*NS
    const int h = idx >> 16, d = (idx >> 10) & 63, s = idx & 1023;
    const int l = h*64 + (s >> 4);
    const int e = ((s & 15) << 6) | d;
    const float freq = expf((float)(e >> 1) * (-2.0f*9.210340371976184f/1024.0f));
    const float ang = (float)l * freq;
    g_pe[idx] = (e & 1) ? cosf(ang) : sinf(ang);
}

// ---------------- kernel 1: posenc-add + QKV MLPs ----------------
// smem: sXHf[8192] | sZ[128*68] | sWf0[4096] | sWf1[4096] = 98KB
#define SMEM1_FLOATS (8192 + 128*PADP + 4096 + 4096)

__device__ __forceinline__ void wfetch(uint32_t dstu, const float* __restrict__ W, int tid)
{
    #pragma unroll
    for (int i = 0; i < 16; ++i) {
        const int fi = tid + i*256;
        const int hi = fi & 1, ln = (fi >> 1) & 31, ks = (fi >> 6) & 7, nt = fi >> 9;
        const int g8 = ln >> 2, tt = ln & 3;
        cp4(dstu + fi*4, W + (ks*8 + tt + 4*hi)*64 + nt*8 + g8);
    }
}

__device__ __forceinline__ void qkv_l1(const float* __restrict__ sXHf,
                                       const float* __restrict__ sWf,
                                       const float* __restrict__ biasg,
                                       float* __restrict__ sZ,
                                       int wid, int lane, int gid, int t4)
{
    const int rA = wid*16 + gid;
    float cc[8][4];
    #pragma unroll
    for (int nt = 0; nt < 8; ++nt) { cc[nt][0]=cc[nt][1]=cc[nt][2]=cc[nt][3]=0.f; }
    #pragma unroll
    for (int ks = 0; ks < 8; ++ks) {
        const float4 av = *(const float4*)&sXHf[((wid*8+ks)*32 + lane)*4];
        #pragma unroll
        for (int nt = 0; nt < 8; ++nt) {
            const float2 bb = *(const float2*)&sWf[((nt*8+ks)*32 + lane)*2];
            mma8(cc[nt], (const float*)&av, (const float*)&bb);
        }
    }
    #pragma unroll
    for (int nt = 0; nt < 8; ++nt) {
        const float2 bv = *(const float2*)&biasg[nt*8 + t4*2];
        #pragma unroll
        for (int r = 0; r < 2; ++r) {
            const int row = rA + 8*r;
            *(float2*)&sZ[row*PADP + nt*8 + t4*2] =
                make_float2(ftanh(cc[nt][2*r] + bv.x), ftanh(cc[nt][2*r+1] + bv.y));
        }
    }
    __syncwarp();   // lanes read cross-lane cols of these rows in l2
}

__device__ __forceinline__ void qkv_l2(float* __restrict__ sZ,
                                       const float* __restrict__ sWf,
                                       const float* __restrict__ biasg,
                                       int wid, int lane, int gid, int t4)
{
    const int rA = wid*16 + gid;
    float cc[8][4];
    #pragma unroll
    for (int nt = 0; nt < 8; ++nt) { cc[nt][0]=cc[nt][1]=cc[nt][2]=cc[nt][3]=0.f; }
    #pragma unroll
    for (int ks = 0; ks < 8; ++ks) {
        const int ac = ks*8 + t4;
        float a[4];
        a[0] = sZ[rA*PADP + ac];
        a[1] = sZ[(rA+8)*PADP + ac];
        a[2] = sZ[rA*PADP + ac + 4];
        a[3] = sZ[(rA+8)*PADP + ac + 4];
        #pragma unroll
        for (int nt = 0; nt < 8; ++nt) {
            const float2 bb = *(const float2*)&sWf[((nt*8+ks)*32 + lane)*2];
            mma8(cc[nt], a, (const float*)&bb);
        }
    }
    __syncwarp();   // all A-reads of this warp's rows done before overwrite
    #pragma unroll
    for (int nt = 0; nt < 8; ++nt) {
        const float2 bv = *(const float2*)&biasg[nt*8 + t4*2];
        #pragma unroll
        for (int r = 0; r < 2; ++r) {
            const int row = rA + 8*r;
            *(float2*)&sZ[row*PADP + nt*8 + t4*2] =
                make_float2(ftanh(cc[nt][2*r] + bv.x), ftanh(cc[nt][2*r+1] + bv.y));
        }
    }
}

__global__ __launch_bounds__(256, 2) void k_qkv(
    const float* __restrict__ x,
    const float* __restrict__ Wq1, const float* __restrict__ bq1,
    const float* __restrict__ Wq2, const float* __restrict__ bq2,
    const float* __restrict__ Wk1, const float* __restrict__ bk1,
    const float* __restrict__ Wk2, const float* __restrict__ bk2,
    const float* __restrict__ Wv1, const float* __restrict__ bv1,
    const float* __restrict__ Wv2, const float* __restrict__ bv2)
{
    extern __shared__ float sm[];
    float* sXHf = sm;                        // [8192]
    float* sZ   = sXHf + 8192;               // [128*68]
    float* sWfA = sZ + 128*PADP;             // [4096]
    float* sWfB = sWfA + 4096;               // [4096]

    const int tid = threadIdx.x;
    const int lane = tid & 31, wid = tid >> 5;
    const int gid = lane >> 2, t4 = lane & 3;
    const int h = blockIdx.z, b = blockIdx.y, bx = blockIdx.x;
    const int s0 = bx * 128;
    const int hb = h*NB + b;

    const float* Wl[6] = {Wq1, Wq2, Wk1, Wk2, Wv1, Wv2};
    const float* Bl[6] = {bq1, bq2, bk1, bk2, bv1, bv2};

    // prefetch W0 directly into frag layout; overlaps posenc work below
    wfetch(su(sWfA), Wl[0] + h*4096, tid);
    CP_COMMIT;

    // xh = x + pe (table lookup), into sZ
    for (int idx = tid; idx < 128*64; idx += 256) {
        const int d = idx >> 7, si = idx & 127;
        const int s = s0 + si;
        sZ[si*PADP + d] = x[(b*NE + (h*64 + d))*NS + s] + g_pe[h*65536 + (d << 10) + s];
    }
    __syncthreads();
    {   // residual persist + xh A-frag build
        float* dst = g_xh + (hb*NS + s0)*ND;
        for (int idx = tid; idx < 128*16; idx += 256) {
            const int si = idx >> 4, d4 = (idx & 15) * 4;
            *(float4*)(dst + si*64 + d4) = *(float4*)&sZ[si*PADP + d4];
        }
        for (int idx = tid; idx < 128*64; idx += 256) {
            const int si = idx >> 6, d = idx & 63;
            const int w = si >> 4, g8 = si & 7, r = (si >> 3) & 1;
            const int ks = d >> 3, tt = d & 3, hi = (d >> 2) & 1;
            sXHf[((w*8+ks)*32 + g8*4 + tt)*4 + r + 2*hi] = sZ[si*PADP + d];
        }
    }
    CP_WAIT0;
    __syncthreads();   // W0 visible; sXHf build complete before l1

    float* cur = sWfA;
    float* nxt = sWfB;

    #pragma unroll 1
    for (int l = 0; l < 6; ++l) {
        if (l < 5) { wfetch(su(nxt), Wl[l+1] + h*4096, tid); CP_COMMIT; }
        if ((l & 1) == 0) {
            qkv_l1(sXHf, cur, Bl[l] + h*64, sZ, wid, lane, gid, t4);
        } else {
            qkv_l2(sZ, cur, Bl[l] + h*64, wid, lane, gid, t4);
            __syncthreads();   // sZ final before block-wide permute reads
            const int p = l >> 1;
            if (p == 0) {          // Q: A-frag tiles, scale folded
                float* qb = g_q + (hb*8 + bx)*8192;
                for (int fi = tid; fi < 8192; fi += 256) {
                    const int rhi = fi & 3, r = rhi & 1, hi = rhi >> 1;
                    const int ln = (fi >> 2) & 31, g8 = ln >> 2, tt = ln & 3;
                    const int ks = (fi >> 7) & 7, w = fi >> 10;
                    qb[fi] = 0.03125f * sZ[(w*16 + g8 + 8*r)*PADP + ks*8 + tt + 4*hi];
                }
            } else if (p == 1) {   // K: B-frag chunks
                float* kb = g_k + (hb*16 + bx*2)*4096;
                for (int idx = tid; idx < 8192; idx += 256) {
                    const int cl = idx >> 12, f = idx & 4095;
                    const int hi = f & 1;
                    const int ln = (f >> 1) & 31, g8 = ln >> 2, tt = ln & 3;
                    const int ks = (f >> 6) & 7, nt = f >> 9;
                    kb[idx] = sZ[(cl*64 + nt*8 + g8)*PADP + ks*8 + tt + 4*hi];
                }
            } else {               // V: k=j, n=d frag chunks
                float* vb = g_v + (hb*16 + bx*2)*4096;
                for (int idx = tid; idx < 8192; idx += 256) {
                    const int cl = idx >> 12, f = idx & 4095;
                    const int hi = f & 1;
                    const int ln = (f >> 1) & 31, g8 = ln >> 2, tt = ln & 3;
                    const int dt = (f >> 6) & 7, ksv = f >> 9;
                    vb[idx] = sZ[(cl*64 + ksv*8 + 4*hi + tt)*PADP + dt*8 + g8];
                }
            }
        }
        if (l < 5) { CP_WAIT0; }
        __syncthreads();   // next W visible; sZ free for reuse
        float* t = cur; cur = nxt; nxt = t;
    }
}

// ---------------- kernel 2: flash attention + residual + LN partial stats ----------
// smem: sQf[8192] | buf0 K/V [8192] | buf1 K/V [8192] = 96KB
#define SMEM2_FLOATS (8192 + 8192 + 8192)

__global__ __launch_bounds__(256, 2) void k_attn()
{
    extern __shared__ float sm[];
    float* sQf  = sm;
    float* buf0 = sm + 8192;
    float* buf1 = sm + 16384;
    const uint32_t b0u = su(buf0), b1u = su(buf1), qfu = su(sQf);

    const int tid = threadIdx.x;
    const int lane = tid & 31, wid = tid >> 5;
    const int gid = lane >> 2, t4 = lane & 3;
    const int rA = wid*16 + gid;

    const int h = blockIdx.z, b = blockIdx.y, bx = blockIdx.x;
    const int hb = h*NB + b;
    const float* qt = g_q + (hb*8 + bx)*8192;
    const float* kb = g_k + hb*16*4096;
    const float* vb = g_v + hb*16*4096;

    // group: Q + chunk0
    #pragma unroll
    for (int i = 0; i < 8; ++i)
        cp16(qfu + (tid + i*256)*16, qt + (tid + i*256)*4);
    #pragma unroll
    for (int i = 0; i < 4; ++i) {
        cp16(b0u + (tid + i*256)*16,         kb + (tid + i*256)*4);
        cp16(b0u + 16384 + (tid + i*256)*16, vb + (tid + i*256)*4);
    }
    CP_COMMIT;

    float l2[2] = {0.f, 0.f};
    float o[8][4];
    #pragma unroll
    for (int nt = 0; nt < 8; ++nt) { o[nt][0]=o[nt][1]=o[nt][2]=o[nt][3]=0.f; }

    const int qsrc1 = (lane & ~3) | (t4 >> 1);
    const int qsrc2 = qsrc1 + 2;
    const bool osel = (t4 & 1);

    #pragma unroll 1
    for (int kt = 0; kt < 16; ++kt) {
        CP_WAIT0;
        __syncthreads();   // chunk kt visible; everyone done with buffer being refilled
        if (kt < 15) {
            const uint32_t bu = ((kt+1) & 1) ? b1u : b0u;
            const float* ksrc = kb + (kt+1)*4096;
            const float* vsrc = vb + (kt+1)*4096;
            #pragma unroll
            for (int i = 0; i < 4; ++i) {
                cp16(bu + (tid + i*256)*16,         ksrc + (tid + i*256)*4);
                cp16(bu + 16384 + (tid + i*256)*16, vsrc + (tid + i*256)*4);
            }
            CP_COMMIT;
        }
        const float* Kf = (kt & 1) ? buf1 : buf0;
        const float* Vf = Kf + 4096;

        // ---- scores = Q K^T ----
        float sc[8][4];
        #pragma unroll
        for (int nt = 0; nt < 8; ++nt) { sc[nt][0]=sc[nt][1]=sc[nt][2]=sc[nt][3]=0.f; }
        #pragma unroll
        for (int ks = 0; ks < 8; ++ks) {
            const float4 av = *(const float4*)&sQf[((wid*8+ks)*32 + lane)*4];
            #pragma unroll
            for (int nt = 0; nt < 8; ++nt) {
                const float2 bb = *(const float2*)&Kf[((nt*8+ks)*32 + lane)*2];
                mma8(sc[nt], (const float*)&av, (const float*)&bb);
            }
        }

        // ---- softmax-lite: |score| <= 2 (tanh inputs), so no max tracking ----
        #pragma unroll
        for (int nt = 0; nt < 8; ++nt) {
            sc[nt][0] = __expf(sc[nt][0]);
            sc[nt][1] = __expf(sc[nt][1]);
            sc[nt][2] = __expf(sc[nt][2]);
            sc[nt][3] = __expf(sc[nt][3]);
            l2[0] += sc[nt][0] + sc[nt][1];
            l2[1] += sc[nt][2] + sc[nt][3];
        }

        // ---- O += P V : P A-frag via intra-quad shuffles ----
        #pragma unroll
        for (int ks = 0; ks < 8; ++ks) {
            const float x0 = __shfl_sync(0xffffffffu, sc[ks][0], qsrc1);
            const float x1 = __shfl_sync(0xffffffffu, sc[ks][1], qsrc1);
            const float x2 = __shfl_sync(0xffffffffu, sc[ks][2], qsrc1);
            const float x3 = __shfl_sync(0xffffffffu, sc[ks][3], qsrc1);
            const float y0 = __shfl_sync(0xffffffffu, sc[ks][0], qsrc2);
            const float y1 = __shfl_sync(0xffffffffu, sc[ks][1], qsrc2);
            const float y2 = __shfl_sync(0xffffffffu, sc[ks][2], qsrc2);
            const float y3 = __shfl_sync(0xffffffffu, sc[ks][3], qsrc2);
            float a[4];
            a[0] = osel ? x1 : x0;   // P(rA,   ks*8+t4)
            a[1] = osel ? x3 : x2;   // P(rA+8, ks*8+t4)
            a[2] = osel ? y1 : y0;   // P(rA,   ks*8+t4+4)
            a[3] = osel ? y3 : y2;   // P(rA+8, ks*8+t4+4)
            #pragma unroll
            for (int dt = 0; dt < 8; ++dt) {
                const float2 bb = *(const float2*)&Vf[((ks*8+dt)*32 + lane)*2];
                mma8(o[dt], a, (const float*)&bb);
            }
        }
    }

    // ---- finalize: reduce l, o/l + residual, LN partials, stage, store ----
    __syncthreads();   // all warps done reading buffers before reuse as sO
    l2[0] += __shfl_xor_sync(0xffffffffu, l2[0], 1);
    l2[0] += __shfl_xor_sync(0xffffffffu, l2[0], 2);
    l2[1] += __shfl_xor_sync(0xffffffffu, l2[1], 1);
    l2[1] += __shfl_xor_sync(0xffffffffu, l2[1], 2);

    float* sO = sm + 8192;   // [128*68] fits in 16384 floats
    {
        const float* xg = g_xh + (hb*NS + bx*128)*ND;
        #pragma unroll
        for (int r = 0; r < 2; ++r) {
            const float inv = 1.0f / l2[r];
            const int row = rA + 8*r;
            float psum = 0.f, psq = 0.f;
            #pragma unroll
            for (int dt = 0; dt < 8; ++dt) {
                const int col = dt*8 + t4*2;
                const float2 xr = *(const float2*)&xg[row*64 + col];
                const float v0 = o[dt][2*r]*inv + xr.x;
                const float v1 = o[dt][2*r+1]*inv + xr.y;
                *(float2*)&sO[row*PADP + col] = make_float2(v0, v1);
                psum += v0 + v1;
                psq  += v0*v0 + v1*v1;
            }
            // quad-reduce (16 cols/lane over t4=0..3 -> 64 cols)
            psum += __shfl_xor_sync(0xffffffffu, psum, 1);
            psum += __shfl_xor_sync(0xffffffffu, psum, 2);
            psq  += __shfl_xor_sync(0xffffffffu, psq, 1);
            psq  += __shfl_xor_sync(0xffffffffu, psq, 2);
            if (t4 == 0) {
                const int si = hb*NS + bx*128 + row;
                g_psum[si] = psum;
                g_psq [si] = psq;
            }
        }
    }
    __syncthreads();
    {
        float* yg = g_y + (size_t)b*NE*NS + (size_t)(h*64)*NS + bx*128;
        for (int idx = tid; idx < 64*128; idx += 256) {
            const int d = idx >> 7, si = idx & 127;
            yg[d*NS + si] = sO[si*PADP + d];
        }
    }
}

// ---------------- kernel 3a: reduce head partials -> mu, rs per (b,s) -----------
__global__ __launch_bounds__(256) void k_stats()
{
    const int idx = blockIdx.x*256 + threadIdx.x;    // over NB*NS = 8192
    const int b = idx >> 10, s = idx & 1023;
    float ts = 0.f, tq = 0.f;
    #pragma unroll
    for (int h = 0; h < NH; ++h) {
        const int o = (h*NB + b)*NS + s;
        ts += g_psum[o];
        tq += g_psq [o];
    }
    const float mu = ts * (1.0f/1024.0f);
    const float var = tq * (1.0f/1024.0f) - mu*mu;
    g_mu[idx] = mu;
    g_rs[idx] = rsqrtf(var + 1e-5f);
}

// ---------------- kernel 3b: single-pass normalize (float4 over s) --------------
__global__ __launch_bounds__(256) void k_ln(const float* __restrict__ gamma,
                                            const float* __restrict__ beta,
                                            float* __restrict__ out)
{
    const int fi = (blockIdx.x*256 + threadIdx.x) * 4;   // over NB*NE*NS
    const int s4 = fi & 1023, e = (fi >> 10) & 1023, b = fi >> 20;
    const float4 yv = *(const float4*)&g_y[fi];
    const float4 mu = *(const float4*)&g_mu[(b << 10) + s4];
    const float4 rs = *(const float4*)&g_rs[(b << 10) + s4];
    const float ga = __ldg(&gamma[e]), be = __ldg(&beta[e]);
    float4 ov;
    ov.x = (yv.x - mu.x)*rs.x*ga + be;
    ov.y = (yv.y - mu.y)*rs.y*ga + be;
    ov.z = (yv.z - mu.z)*rs.z*ga + be;
    ov.w = (yv.w - mu.w)*rs.w*ga + be;
    *(float4*)&out[fi] = ov;
}

// ---------------- launcher ----------------
extern "C" void kernel_launch(void* const* d_in, const int* in_sizes, int n_in,
                              void* d_out, int out_size)
{
    (void)in_sizes; (void)n_in; (void)out_size;
    const float* x   = (const float*)d_in[0];
    const float* Wq1 = (const float*)d_in[1];  const float* bq1 = (const float*)d_in[2];
    const float* Wq2 = (const float*)d_in[3];  const float* bq2 = (const float*)d_in[4];
    const float* Wk1 = (const float*)d_in[5];  const float* bk1 = (const float*)d_in[6];
    const float* Wk2 = (const float*)d_in[7];  const float* bk2 = (const float*)d_in[8];
    const float* Wv1 = (const float*)d_in[9];  const float* bv1 = (const float*)d_in[10];
    const float* Wv2 = (const float*)d_in[11]; const float* bv2 = (const float*)d_in[12];
    const float* gamma = (const float*)d_in[13];
    const float* beta  = (const float*)d_in[14];
    float* out = (float*)d_out;

    const int smem1 = SMEM1_FLOATS * (int)sizeof(float);
    const int smem2 = SMEM2_FLOATS * (int)sizeof(float);
    cudaFuncSetAttribute(k_qkv,  cudaFuncAttributeMaxDynamicSharedMemorySize, smem1);
    cudaFuncSetAttribute(k_attn, cudaFuncAttributeMaxDynamicSharedMemorySize, smem2);

    k_pe<<<NH*ND*NS/256, 256>>>();

    dim3 g1(NS/128, NB, NH);
    k_qkv<<<g1, 256, smem1>>>(x, Wq1, bq1, Wq2, bq2, Wk1, bk1, Wk2, bk2, Wv1, bv1, Wv2, bv2);

    dim3 g2(NS/128, NB, NH);
    k_attn<<<g2, 256, smem2>>>();

    k_stats<<<NB*NS/256, 256>>>();
    k_ln<<<NB*NE*NS/1024, 256>>>(gamma, beta, out);
}

// round 9
// speedup vs baseline: 3.4163x; 1.0055x over previous
#include <cuda_runtime.h>
#include <math.h>
#include <stdint.h>

#define NB 8
#define NH 16
#define ND 64
#define NS 1024
#define NE 1024
#define PADP 68   // row stride: 68 % 32 == 4 -> conflict-free row-set accesses

// ---------------- scratch ----------------
__device__ float g_pe[NH*ND*NS];     // (h,d,s) positional encoding
__device__ float g_xh[NH*NB*NS*ND];  // (h,b,s,d) pos-encoded input (residual), fp32
__device__ float g_q [NH*NB*NS*ND];  // A-frag layout per 128-row tile, scale folded
__device__ float g_k [NH*NB*NS*ND];  // B-frag layout per 64-row chunk
__device__ float g_v [NH*NB*NS*ND];  // B-frag (V role) layout per 64-row chunk
__device__ float g_y [NB*NE*NS];     // (b,e,s) pre-layernorm
__device__ float g_psum[NH*NB*NS];   // per-head partial sum of y over its 64 dims
__device__ float g_psq [NH*NB*NS];   // per-head partial sum of y^2
__device__ float g_mu[NB*NS];        // layernorm mean
__device__ float g_rs[NB*NS];        // layernorm rsqrt(var+eps)

// ---------------- helpers ----------------
__device__ __forceinline__ float ftanh(float x) {
    const float e = __expf(2.0f * x);
    return 1.0f - __fdividef(2.0f, e + 1.0f);
}
__device__ __forceinline__ void mma8(float* c, const float* a, const float* b) {
    asm volatile(
        "mma.sync.aligned.m16n8k8.row.col.f32.tf32.tf32.f32 "
        "{%0,%1,%2,%3}, {%4,%5,%6,%7}, {%8,%9}, {%0,%1,%2,%3};\n"
        : "+f"(c[0]), "+f"(c[1]), "+f"(c[2]), "+f"(c[3])
        : "r"(__float_as_uint(a[0])), "r"(__float_as_uint(a[1])),
          "r"(__float_as_uint(a[2])), "r"(__float_as_uint(a[3])),
          "r"(__float_as_uint(b[0])), "r"(__float_as_uint(b[1])));
}
__device__ __forceinline__ uint32_t su(const void* p) {
    return (uint32_t)__cvta_generic_to_shared(p);
}
__device__ __forceinline__ void cp16(uint32_t s, const void* g) {
    asm volatile("cp.async.cg.shared.global [%0], [%1], 16;\n" :: "r"(s), "l"(g));
}
__device__ __forceinline__ void cp4(uint32_t s, const void* g) {
    asm volatile("cp.async.ca.shared.global [%0], [%1], 4;\n" :: "r"(s), "l"(g));
}
#define CP_COMMIT asm volatile("cp.async.commit_group;\n" ::: "memory")
#define CP_WAIT0  asm volatile("cp.async.wait_group 0;\n" ::: "memory")
#define PAIR_BAR(rw) asm volatile("bar.sync %0, 64;" :: "r"((rw)+1) : "memory")

// ---------------- kernel 0: positional encoding table, (h,d,s) layout ----------------
// one sincosf covers the (d=2m, d=2m+1) pair (shared angle)
__global__ __launch_bounds__(256) void k_pe()
{
    const int idx = blockIdx.x*256 + threadIdx.x;   // over NH*(ND/2)*NS
    const int h = idx >> 15;
    const int m = (idx >> 10) & 31;
    const int s = idx & 1023;
    const int l = h*64 + (s >> 4);
    const int eh = ((s & 15) << 5) | m;             // e>>1 for both pair members
    const float freq = __expf((float)eh * (-2.0f*9.210340371976184f/1024.0f));
    float sv, cv;
    sincosf((float)l * freq, &sv, &cv);
    const int base = h*65536 + (m << 11) + s;       // d=2m
    g_pe[base]        = sv;                         // even e -> sin
    g_pe[base + 1024] = cv;                         // odd e  -> cos
}

// ---------------- kernel 1: posenc-add + QKV MLPs (512 threads, nt-split) --------
// smem: sXHf[8192] | sZ[128*68] | sWf0[4096] | sWf1[4096] = 98KB
#define SMEM1_FLOATS (8192 + 128*PADP + 4096 + 4096)

__device__ __forceinline__ void wfetch(uint32_t dstu, const float* __restrict__ W, int tid)
{
    #pragma unroll
    for (int i = 0; i < 8; ++i) {
        const int fi = tid + i*512;
        const int hi = fi & 1, ln = (fi >> 1) & 31, ks = (fi >> 6) & 7, nt = fi >> 9;
        const int g8 = ln >> 2, tt = ln & 3;
        cp4(dstu + fi*4, W + (ks*8 + tt + 4*hi)*64 + nt*8 + g8);
    }
}

// layer 1: A from sXHf (LDS.128 frags), nt-half per warp, out rows rA -> sZ
__device__ __forceinline__ void qkv_l1(const float* __restrict__ sXHf,
                                       const float* __restrict__ sWf,
                                       const float* __restrict__ biasg,
                                       float* __restrict__ sZ,
                                       int rw, int nh, int lane, int gid, int t4)
{
    const int rA = rw*16 + gid;
    float cc[4][4];
    #pragma unroll
    for (int nt = 0; nt < 4; ++nt) { cc[nt][0]=cc[nt][1]=cc[nt][2]=cc[nt][3]=0.f; }
    #pragma unroll
    for (int ks = 0; ks < 8; ++ks) {
        const float4 av = *(const float4*)&sXHf[((rw*8+ks)*32 + lane)*4];
        #pragma unroll
        for (int nt = 0; nt < 4; ++nt) {
            const float2 bb = *(const float2*)&sWf[(((nh*4+nt)*8+ks)*32 + lane)*2];
            mma8(cc[nt], (const float*)&av, (const float*)&bb);
        }
    }
    #pragma unroll
    for (int nt = 0; nt < 4; ++nt) {
        const int col = (nh*4+nt)*8 + t4*2;
        const float2 bv = *(const float2*)&biasg[col];
        #pragma unroll
        for (int r = 0; r < 2; ++r) {
            const int row = rA + 8*r;
            *(float2*)&sZ[row*PADP + col] =
                make_float2(ftanh(cc[nt][2*r] + bv.x), ftanh(cc[nt][2*r+1] + bv.y));
        }
    }
    PAIR_BAR(rw);   // pair (rw, nh=0/1) wrote both col halves of rows rA
}

// layer 2: A scalar from sZ (all ks), nt-half per warp, overwrite sZ rows rA
__device__ __forceinline__ void qkv_l2(float* __restrict__ sZ,
                                       const float* __restrict__ sWf,
                                       const float* __restrict__ biasg,
                                       int rw, int nh, int lane, int gid, int t4)
{
    const int rA = rw*16 + gid;
    float cc[4][4];
    #pragma unroll
    for (int nt = 0; nt < 4; ++nt) { cc[nt][0]=cc[nt][1]=cc[nt][2]=cc[nt][3]=0.f; }
    #pragma unroll
    for (int ks = 0; ks < 8; ++ks) {
        const int ac = ks*8 + t4;
        float a[4];
        a[0] = sZ[rA*PADP + ac];
        a[1] = sZ[(rA+8)*PADP + ac];
        a[2] = sZ[rA*PADP + ac + 4];
        a[3] = sZ[(rA+8)*PADP + ac + 4];
        #pragma unroll
        for (int nt = 0; nt < 4; ++nt) {
            const float2 bb = *(const float2*)&sWf[(((nh*4+nt)*8+ks)*32 + lane)*2];
            mma8(cc[nt], a, (const float*)&bb);
        }
    }
    PAIR_BAR(rw);   // both pair warps done reading rows rA before overwrite
    #pragma unroll
    for (int nt = 0; nt < 4; ++nt) {
        const int col = (nh*4+nt)*8 + t4*2;
        const float2 bv = *(const float2*)&biasg[col];
        #pragma unroll
        for (int r = 0; r < 2; ++r) {
            const int row = rA + 8*r;
            *(float2*)&sZ[row*PADP + col] =
                make_float2(ftanh(cc[nt][2*r] + bv.x), ftanh(cc[nt][2*r+1] + bv.y));
        }
    }
}

__global__ __launch_bounds__(512, 2) void k_qkv(
    const float* __restrict__ x,
    const float* __restrict__ Wq1, const float* __restrict__ bq1,
    const float* __restrict__ Wq2, const float* __restrict__ bq2,
    const float* __restrict__ Wk1, const float* __restrict__ bk1,
    const float* __restrict__ Wk2, const float* __restrict__ bk2,
    const float* __restrict__ Wv1, const float* __restrict__ bv1,
    const float* __restrict__ Wv2, const float* __restrict__ bv2)
{
    extern __shared__ float sm[];
    float* sXHf = sm;                        // [8192]
    float* sZ   = sXHf + 8192;               // [128*68]
    float* sWfA = sZ + 128*PADP;             // [4096]
    float* sWfB = sWfA + 4096;               // [4096]

    const int tid = threadIdx.x;
    const int lane = tid & 31, wid = tid >> 5;
    const int gid = lane >> 2, t4 = lane & 3;
    const int rw = wid & 7, nh = wid >> 3;
    const int h = blockIdx.z, b = blockIdx.y, bx = blockIdx.x;
    const int s0 = bx * 128;
    const int hb = h*NB + b;

    const float* Wl[6] = {Wq1, Wq2, Wk1, Wk2, Wv1, Wv2};
    const float* Bl[6] = {bq1, bq2, bk1, bk2, bv1, bv2};

    // prefetch W0 directly into frag layout; overlaps posenc work below
    wfetch(su(sWfA), Wl[0] + h*4096, tid);
    CP_COMMIT;

    // xh = x + pe (table lookup), into sZ
    for (int idx = tid; idx < 128*64; idx += 512) {
        const int d = idx >> 7, si = idx & 127;
        const int s = s0 + si;
        sZ[si*PADP + d] = x[(b*NE + (h*64 + d))*NS + s] + g_pe[h*65536 + (d << 10) + s];
    }
    __syncthreads();
    {   // residual persist + xh A-frag build
        float* dst = g_xh + (hb*NS + s0)*ND;
        for (int idx = tid; idx < 128*16; idx += 512) {
            const int si = idx >> 4, d4 = (idx & 15) * 4;
            *(float4*)(dst + si*64 + d4) = *(float4*)&sZ[si*PADP + d4];
        }
        for (int idx = tid; idx < 128*64; idx += 512) {
            const int si = idx >> 6, d = idx & 63;
            const int w = si >> 4, g8 = si & 7, r = (si >> 3) & 1;
            const int ks = d >> 3, tt = d & 3, hi = (d >> 2) & 1;
            sXHf[((w*8+ks)*32 + g8*4 + tt)*4 + r + 2*hi] = sZ[si*PADP + d];
        }
    }
    CP_WAIT0;
    __syncthreads();   // W0 visible; sXHf build complete before l1

    float* cur = sWfA;
    float* nxt = sWfB;

    #pragma unroll 1
    for (int l = 0; l < 6; ++l) {
        if (l < 5) { wfetch(su(nxt), Wl[l+1] + h*4096, tid); CP_COMMIT; }
        if ((l & 1) == 0) {
            qkv_l1(sXHf, cur, Bl[l] + h*64, sZ, rw, nh, lane, gid, t4);
        } else {
            qkv_l2(sZ, cur, Bl[l] + h*64, rw, nh, lane, gid, t4);
            __syncthreads();   // sZ final before block-wide permute reads
            const int p = l >> 1;
            if (p == 0) {          // Q: A-frag tiles, scale folded
                float* qb = g_q + (hb*8 + bx)*8192;
                for (int fi = tid; fi < 8192; fi += 512) {
                    const int rhi = fi & 3, r = rhi & 1, hi = rhi >> 1;
                    const int ln = (fi >> 2) & 31, g8 = ln >> 2, tt = ln & 3;
                    const int ks = (fi >> 7) & 7, w = fi >> 10;
                    qb[fi] = 0.03125f * sZ[(w*16 + g8 + 8*r)*PADP + ks*8 + tt + 4*hi];
                }
            } else if (p == 1) {   // K: B-frag chunks
                float* kb = g_k + (hb*16 + bx*2)*4096;
                for (int idx = tid; idx < 8192; idx += 512) {
                    const int cl = idx >> 12, f = idx & 4095;
                    const int hi = f & 1;
                    const int ln = (f >> 1) & 31, g8 = ln >> 2, tt = ln & 3;
                    const int ks = (f >> 6) & 7, nt = f >> 9;
                    kb[idx] = sZ[(cl*64 + nt*8 + g8)*PADP + ks*8 + tt + 4*hi];
                }
            } else {               // V: k=j, n=d frag chunks
                float* vb = g_v + (hb*16 + bx*2)*4096;
                for (int idx = tid; idx < 8192; idx += 512) {
                    const int cl = idx >> 12, f = idx & 4095;
                    const int hi = f & 1;
                    const int ln = (f >> 1) & 31, g8 = ln >> 2, tt = ln & 3;
                    const int dt = (f >> 6) & 7, ksv = f >> 9;
                    vb[idx] = sZ[(cl*64 + ksv*8 + 4*hi + tt)*PADP + dt*8 + g8];
                }
            }
        }
        if (l < 5) { CP_WAIT0; }
        __syncthreads();   // next W visible; sZ free for reuse
        float* t = cur; cur = nxt; nxt = t;
    }
}

// ---------------- kernel 2: flash attention + residual + LN partial stats ----------
// smem: sQf[8192] | buf0 K/V [8192] | buf1 K/V [8192] = 96KB
#define SMEM2_FLOATS (8192 + 8192 + 8192)

__global__ __launch_bounds__(256, 2) void k_attn()
{
    extern __shared__ float sm[];
    float* sQf  = sm;
    float* buf0 = sm + 8192;
    float* buf1 = sm + 16384;
    const uint32_t b0u = su(buf0), b1u = su(buf1), qfu = su(sQf);

    const int tid = threadIdx.x;
    const int lane = tid & 31, wid = tid >> 5;
    const int gid = lane >> 2, t4 = lane & 3;
    const int rA = wid*16 + gid;

    const int h = blockIdx.z, b = blockIdx.y, bx = blockIdx.x;
    const int hb = h*NB + b;
    const float* qt = g_q + (hb*8 + bx)*8192;
    const float* kb = g_k + hb*16*4096;
    const float* vb = g_v + hb*16*4096;

    // group: Q + chunk0
    #pragma unroll
    for (int i = 0; i < 8; ++i)
        cp16(qfu + (tid + i*256)*16, qt + (tid + i*256)*4);
    #pragma unroll
    for (int i = 0; i < 4; ++i) {
        cp16(b0u + (tid + i*256)*16,         kb + (tid + i*256)*4);
        cp16(b0u + 16384 + (tid + i*256)*16, vb + (tid + i*256)*4);
    }
    CP_COMMIT;

    float l2[2] = {0.f, 0.f};
    float o[8][4];
    #pragma unroll
    for (int nt = 0; nt < 8; ++nt) { o[nt][0]=o[nt][1]=o[nt][2]=o[nt][3]=0.f; }

    const int qsrc1 = (lane & ~3) | (t4 >> 1);
    const int qsrc2 = qsrc1 + 2;
    const bool osel = (t4 & 1);

    #pragma unroll 1
    for (int kt = 0; kt < 16; ++kt) {
        CP_WAIT0;
        __syncthreads();   // chunk kt visible; everyone done with buffer being refilled
        if (kt < 15) {
            const uint32_t bu = ((kt+1) & 1) ? b1u : b0u;
            const float* ksrc = kb + (kt+1)*4096;
            const float* vsrc = vb + (kt+1)*4096;
            #pragma unroll
            for (int i = 0; i < 4; ++i) {
                cp16(bu + (tid + i*256)*16,         ksrc + (tid + i*256)*4);
                cp16(bu + 16384 + (tid + i*256)*16, vsrc + (tid + i*256)*4);
            }
            CP_COMMIT;
        }
        const float* Kf = (kt & 1) ? buf1 : buf0;
        const float* Vf = Kf + 4096;

        // ---- scores = Q K^T ----
        float sc[8][4];
        #pragma unroll
        for (int nt = 0; nt < 8; ++nt) { sc[nt][0]=sc[nt][1]=sc[nt][2]=sc[nt][3]=0.f; }
        #pragma unroll
        for (int ks = 0; ks < 8; ++ks) {
            const float4 av = *(const float4*)&sQf[((wid*8+ks)*32 + lane)*4];
            #pragma unroll
            for (int nt = 0; nt < 8; ++nt) {
                const float2 bb = *(const float2*)&Kf[((nt*8+ks)*32 + lane)*2];
                mma8(sc[nt], (const float*)&av, (const float*)&bb);
            }
        }

        // ---- softmax-lite: |score| <= 2 (tanh inputs), so no max tracking ----
        #pragma unroll
        for (int nt = 0; nt < 8; ++nt) {
            sc[nt][0] = __expf(sc[nt][0]);
            sc[nt][1] = __expf(sc[nt][1]);
            sc[nt][2] = __expf(sc[nt][2]);
            sc[nt][3] = __expf(sc[nt][3]);
            l2[0] += sc[nt][0] + sc[nt][1];
            l2[1] += sc[nt][2] + sc[nt][3];
        }

        // ---- O += P V : P A-frag via intra-quad shuffles ----
        #pragma unroll
        for (int ks = 0; ks < 8; ++ks) {
            const float x0 = __shfl_sync(0xffffffffu, sc[ks][0], qsrc1);
            const float x1 = __shfl_sync(0xffffffffu, sc[ks][1], qsrc1);
            const float x2 = __shfl_sync(0xffffffffu, sc[ks][2], qsrc1);
            const float x3 = __shfl_sync(0xffffffffu, sc[ks][3], qsrc1);
            const float y0 = __shfl_sync(0xffffffffu, sc[ks][0], qsrc2);
            const float y1 = __shfl_sync(0xffffffffu, sc[ks][1], qsrc2);
            const float y2 = __shfl_sync(0xffffffffu, sc[ks][2], qsrc2);
            const float y3 = __shfl_sync(0xffffffffu, sc[ks][3], qsrc2);
            float a[4];
            a[0] = osel ? x1 : x0;   // P(rA,   ks*8+t4)
            a[1] = osel ? x3 : x2;   // P(rA+8, ks*8+t4)
            a[2] = osel ? y1 : y0;   // P(rA,   ks*8+t4+4)
            a[3] = osel ? y3 : y2;   // P(rA+8, ks*8+t4+4)
            #pragma unroll
            for (int dt = 0; dt < 8; ++dt) {
                const float2 bb = *(const float2*)&Vf[((ks*8+dt)*32 + lane)*2];
                mma8(o[dt], a, (const float*)&bb);
            }
        }
    }

    // ---- finalize: reduce l, o/l + residual, LN partials, stage, store ----
    __syncthreads();   // all warps done reading buffers before reuse as sO
    l2[0] += __shfl_xor_sync(0xffffffffu, l2[0], 1);
    l2[0] += __shfl_xor_sync(0xffffffffu, l2[0], 2);
    l2[1] += __shfl_xor_sync(0xffffffffu, l2[1], 1);
    l2[1] += __shfl_xor_sync(0xffffffffu, l2[1], 2);

    float* sO = sm + 8192;   // [128*68] fits in 16384 floats
    {
        const float* xg = g_xh + (hb*NS + bx*128)*ND;
        #pragma unroll
        for (int r = 0; r < 2; ++r) {
            const float inv = 1.0f / l2[r];
            const int row = rA + 8*r;
            float psum = 0.f, psq = 0.f;
            #pragma unroll
            for (int dt = 0; dt < 8; ++dt) {
                const int col = dt*8 + t4*2;
                const float2 xr = *(const float2*)&xg[row*64 + col];
                const float v0 = o[dt][2*r]*inv + xr.x;
                const float v1 = o[dt][2*r+1]*inv + xr.y;
                *(float2*)&sO[row*PADP + col] = make_float2(v0, v1);
                psum += v0 + v1;
                psq  += v0*v0 + v1*v1;
            }
            psum += __shfl_xor_sync(0xffffffffu, psum, 1);
            psum += __shfl_xor_sync(0xffffffffu, psum, 2);
            psq  += __shfl_xor_sync(0xffffffffu, psq, 1);
            psq  += __shfl_xor_sync(0xffffffffu, psq, 2);
            if (t4 == 0) {
                const int si = hb*NS + bx*128 + row;
                g_psum[si] = psum;
                g_psq [si] = psq;
            }
        }
    }
    __syncthreads();
    {
        float* yg = g_y + (size_t)b*NE*NS + (size_t)(h*64)*NS + bx*128;
        for (int idx = tid; idx < 64*128; idx += 256) {
            const int d = idx >> 7, si = idx & 127;
            yg[d*NS + si] = sO[si*PADP + d];
        }
    }
}

// ---------------- kernel 3a: reduce head partials -> mu, rs per (b,s) -----------
__global__ __launch_bounds__(256) void k_stats()
{
    const int idx = blockIdx.x*256 + threadIdx.x;    // over NB*NS = 8192
    const int b = idx >> 10, s = idx & 1023;
    float ts = 0.f, tq = 0.f;
    #pragma unroll
    for (int h = 0; h < NH; ++h) {
        const int o = (h*NB + b)*NS + s;
        ts += g_psum[o];
        tq += g_psq [o];
    }
    const float mu = ts * (1.0f/1024.0f);
    const float var = tq * (1.0f/1024.0f) - mu*mu;
    g_mu[idx] = mu;
    g_rs[idx] = rsqrtf(var + 1e-5f);
}

// ---------------- kernel 3b: single-pass normalize (float4 over s) --------------
__global__ __launch_bounds__(256) void k_ln(const float* __restrict__ gamma,
                                            const float* __restrict__ beta,
                                            float* __restrict__ out)
{
    const int fi = (blockIdx.x*256 + threadIdx.x) * 4;   // over NB*NE*NS
    const int s4 = fi & 1023, e = (fi >> 10) & 1023, b = fi >> 20;
    const float4 yv = *(const float4*)&g_y[fi];
    const float4 mu = *(const float4*)&g_mu[(b << 10) + s4];
    const float4 rs = *(const float4*)&g_rs[(b << 10) + s4];
    const float ga = __ldg(&gamma[e]), be = __ldg(&beta[e]);
    float4 ov;
    ov.x = (yv.x - mu.x)*rs.x*ga + be;
    ov.y = (yv.y - mu.y)*rs.y*ga + be;
    ov.z = (yv.z - mu.z)*rs.z*ga + be;
    ov.w = (yv.w - mu.w)*rs.w*ga + be;
    *(float4*)&out[fi] = ov;
}

// ---------------- launcher ----------------
extern "C" void kernel_launch(void* const* d_in, const int* in_sizes, int n_in,
                              void* d_out, int out_size)
{
    (void)in_sizes; (void)n_in; (void)out_size;
    const float* x   = (const float*)d_in[0];
    const float* Wq1 = (const float*)d_in[1];  const float* bq1 = (const float*)d_in[2];
    const float* Wq2 = (const float*)d_in[3];  const float* bq2 = (const float*)d_in[4];
    const float* Wk1 = (const float*)d_in[5];  const float* bk1 = (const float*)d_in[6];
    const float* Wk2 = (const float*)d_in[7];  const float* bk2 = (const float*)d_in[8];
    const float* Wv1 = (const float*)d_in[9];  const float* bv1 = (const float*)d_in[10];
    const float* Wv2 = (const float*)d_in[11]; const float* bv2 = (const float*)d_in[12];
    const float* gamma = (const float*)d_in[13];
    const float* beta  = (const float*)d_in[14];
    float* out = (float*)d_out;

    const int smem1 = SMEM1_FLOATS * (int)sizeof(float);
    const int smem2 = SMEM2_FLOATS * (int)sizeof(float);
    cudaFuncSetAttribute(k_qkv,  cudaFuncAttributeMaxDynamicSharedMemorySize, smem1);
    cudaFuncSetAttribute(k_attn, cudaFuncAttributeMaxDynamicSharedMemorySize, smem2);

    k_pe<<<NH*(ND/2)*NS/256, 256>>>();

    dim3 g1(NS/128, NB, NH);
    k_qkv<<<g1, 512, smem1>>>(x, Wq1, bq1, Wq2, bq2, Wk1, bk1, Wk2, bk2, Wv1, bv1, Wv2, bv2);

    dim3 g2(NS/128, NB, NH);
    k_attn<<<g2, 256, smem2>>>();

    k_stats<<<NB*NS/256, 256>>>();
    k_ln<<<NB*NE*NS/1024, 256>>>(gamma, beta, out);
}